// round 1
// baseline (speedup 1.0000x reference)
#include <cuda_runtime.h>
#include <math.h>

#define BATCH  4096
#define OBSD   512
#define DH     1024
#define NEXP   8
#define DKK    256
#define DVV    1024
#define NTASKS 10
#define NOUT   128

// ---------------- scratch (device globals: no allocation allowed) ----------
__device__ float g_h1 [BATCH * DH];
__device__ float g_h  [BATCH * DH];
__device__ float g_e1 [BATCH * DH];
__device__ float g_e2 [BATCH * DH];
__device__ float g_res[BATCH * DVV];
__device__ float g_t  [BATCH * DH];
__device__ float g_q  [DKK];
__device__ float g_wn [NEXP * DH];
__device__ float g_cn [NEXP];
__device__ float g_s  [BATCH];

// ---------------- tiled fp32 GEMM ------------------------------------------
#define BM 128
#define BN 128
#define BK 16

enum { EPI_RELU = 0, EPI_SCALE = 1, EPI_SPLIT = 2 };

// C[M,N] = epilogue(A[M,K] @ B[K,N] + bias)
//  EPI_RELU : C = relu(acc + bias[col])
//  EPI_SCALE: C = beta*C + (acc + bias[col]) * scale[row]
//  EPI_SPLIT: N==128; col<64 -> mean, col>=64 -> std/log_std (clip + exp)
template <int EPI>
__global__ __launch_bounds__(256, 2)
void gemm_k(const float* __restrict__ A, const float* __restrict__ Bm,
            const float* __restrict__ bias, float* __restrict__ C,
            int M, int N, int K,
            const float* __restrict__ scale, int beta)
{
    __shared__ float As[2][BK][BM + 4];   // +4 pad keeps 16B align, cuts conflicts
    __shared__ float Bs[2][BK][BN];

    const int tid = threadIdx.x;
    const int bm0 = blockIdx.y * BM;
    const int bn0 = blockIdx.x * BN;

    // global->smem load mapping
    const int a_row = tid >> 2;            // 0..63 (and +64 for second chunk)
    const int a_col = (tid & 3) << 2;      // 0,4,8,12
    const int b_row = tid >> 5;            // 0..7  (and +8)
    const int b_col = (tid & 31) << 2;     // 0..124

    const float* Ag = A  + (size_t)(bm0 + a_row) * K + a_col;
    const float* Bg = Bm + (size_t)b_row * N + bn0 + b_col;

    const int ty = tid >> 4;               // 0..15
    const int tx = tid & 15;               // 0..15

    float acc[8][8];
#pragma unroll
    for (int i = 0; i < 8; i++)
#pragma unroll
        for (int j = 0; j < 8; j++) acc[i][j] = 0.f;

    // prologue: tile 0 -> stage 0
    {
        float4 a0 = *(const float4*)(Ag);
        float4 a1 = *(const float4*)(Ag + (size_t)64 * K);
        float4 b0 = *(const float4*)(Bg);
        float4 b1 = *(const float4*)(Bg + (size_t)8 * N);
        As[0][a_col + 0][a_row] = a0.x; As[0][a_col + 1][a_row] = a0.y;
        As[0][a_col + 2][a_row] = a0.z; As[0][a_col + 3][a_row] = a0.w;
        As[0][a_col + 0][a_row + 64] = a1.x; As[0][a_col + 1][a_row + 64] = a1.y;
        As[0][a_col + 2][a_row + 64] = a1.z; As[0][a_col + 3][a_row + 64] = a1.w;
        *(float4*)&Bs[0][b_row][b_col]     = b0;
        *(float4*)&Bs[0][b_row + 8][b_col] = b1;
    }
    __syncthreads();

    const int KT = K / BK;
    int stage = 0;
    for (int kt = 0; kt < KT; kt++) {
        float4 a0, a1, b0, b1;
        if (kt + 1 < KT) {                       // prefetch next tile into regs
            const float* Ag2 = Ag + (kt + 1) * BK;
            const float* Bg2 = Bg + (size_t)(kt + 1) * BK * N;
            a0 = *(const float4*)(Ag2);
            a1 = *(const float4*)(Ag2 + (size_t)64 * K);
            b0 = *(const float4*)(Bg2);
            b1 = *(const float4*)(Bg2 + (size_t)8 * N);
        }
#pragma unroll
        for (int k = 0; k < BK; k++) {
            float av[8], bw[8];
            *(float4*)&av[0] = *(const float4*)&As[stage][k][ty * 8];
            *(float4*)&av[4] = *(const float4*)&As[stage][k][ty * 8 + 4];
            *(float4*)&bw[0] = *(const float4*)&Bs[stage][k][tx * 8];
            *(float4*)&bw[4] = *(const float4*)&Bs[stage][k][tx * 8 + 4];
#pragma unroll
            for (int i = 0; i < 8; i++)
#pragma unroll
                for (int j = 0; j < 8; j++)
                    acc[i][j] += av[i] * bw[j];
        }
        if (kt + 1 < KT) {
            const int ns = stage ^ 1;
            As[ns][a_col + 0][a_row] = a0.x; As[ns][a_col + 1][a_row] = a0.y;
            As[ns][a_col + 2][a_row] = a0.z; As[ns][a_col + 3][a_row] = a0.w;
            As[ns][a_col + 0][a_row + 64] = a1.x; As[ns][a_col + 1][a_row + 64] = a1.y;
            As[ns][a_col + 2][a_row + 64] = a1.z; As[ns][a_col + 3][a_row + 64] = a1.w;
            *(float4*)&Bs[ns][b_row][b_col]     = b0;
            *(float4*)&Bs[ns][b_row + 8][b_col] = b1;
            __syncthreads();
            stage = ns;
        }
    }

    // ------------- epilogue -------------
    const int row0 = bm0 + ty * 8;
    const int col0 = bn0 + tx * 8;
    float bsv[8];
    *(float4*)&bsv[0] = *(const float4*)&bias[col0];
    *(float4*)&bsv[4] = *(const float4*)&bias[col0 + 4];

    if (EPI == EPI_RELU) {
#pragma unroll
        for (int i = 0; i < 8; i++) {
            float* Cr = C + (size_t)(row0 + i) * N + col0;
            float o[8];
#pragma unroll
            for (int j = 0; j < 8; j++) {
                float v = acc[i][j] + bsv[j];
                o[j] = v > 0.f ? v : 0.f;
            }
            *(float4*)Cr       = *(float4*)&o[0];
            *(float4*)(Cr + 4) = *(float4*)&o[4];
        }
    } else if (EPI == EPI_SCALE) {
#pragma unroll
        for (int i = 0; i < 8; i++) {
            float s = scale[row0 + i];
            float* Cr = C + (size_t)(row0 + i) * N + col0;
            float o[8];
            if (beta) {
                *(float4*)&o[0] = *(const float4*)Cr;
                *(float4*)&o[4] = *(const float4*)(Cr + 4);
            } else {
#pragma unroll
                for (int j = 0; j < 8; j++) o[j] = 0.f;
            }
#pragma unroll
            for (int j = 0; j < 8; j++)
                o[j] += (acc[i][j] + bsv[j]) * s;
            *(float4*)Cr       = *(float4*)&o[0];
            *(float4*)(Cr + 4) = *(float4*)&o[4];
        }
    } else {  // EPI_SPLIT: out layout = [mean(B*64) | std(B*64) | log_std(B*64)]
#pragma unroll
        for (int i = 0; i < 8; i++) {
            const int r = row0 + i;
#pragma unroll
            for (int j = 0; j < 8; j++) {
                const int c = col0 + j;
                float v = acc[i][j] + bsv[j];
                if (c < 64) {
                    C[(size_t)r * 64 + c] = v;
                } else {
                    float ls = fminf(fmaxf(v, -20.f), 2.f);
                    C[(size_t)BATCH * 64 + (size_t)r * 64 + (c - 64)] = expf(ls);
                    C[(size_t)2 * BATCH * 64 + (size_t)r * 64 + (c - 64)] = ls;
                }
            }
        }
    }
}

// q = Wq[t][t,:] + bq[t];  cn[n] = dot(bk[n], q)
__global__ void prep_k(const float* __restrict__ Wq, const float* __restrict__ bq,
                       const float* __restrict__ bk, const int* __restrict__ task_id)
{
    __shared__ float qs[DKK];
    const int t = *task_id;
    const int tid = threadIdx.x;   // 256 threads
    float qv = Wq[(size_t)(t * NTASKS + t) * DKK + tid] + bq[(size_t)t * DKK + tid];
    g_q[tid] = qv;
    qs[tid]  = qv;
    __syncthreads();
    const int w = tid >> 5, lane = tid & 31;
    float sum = 0.f;
#pragma unroll
    for (int k = lane; k < DKK; k += 32) sum += bk[(size_t)w * DKK + k] * qs[k];
#pragma unroll
    for (int o = 16; o; o >>= 1) sum += __shfl_xor_sync(0xffffffffu, sum, o);
    if (lane == 0) g_cn[w] = sum;
}

// wn[n][d] = dot(Wk[n][d,:], q)
__global__ void wn_k(const float* __restrict__ Wk)
{
    __shared__ float qs[DKK];
    const int tid = threadIdx.x;   // 256
    qs[tid] = g_q[tid];
    __syncthreads();
    const int idx = blockIdx.x * 256 + tid;   // 0..NEXP*DH-1
    const float* wr = Wk + (size_t)idx * DKK;
    float sum = 0.f;
#pragma unroll 8
    for (int k = 0; k < DKK; k++) sum += wr[k] * qs[k];
    g_wn[idx] = sum;
}

// s[b] = dot(e2[b,:], wn[n]) + cn[n]
__global__ void expkq_k(const float* __restrict__ e2, int n)
{
    __shared__ float ws[DH];
    const int tid = threadIdx.x;   // 256
    for (int i = tid; i < DH; i += 256) ws[i] = g_wn[(size_t)n * DH + i];
    __syncthreads();
    const int w = tid >> 5, lane = tid & 31;
    const int row = blockIdx.x * 8 + w;
    const float* er = e2 + (size_t)row * DH;
    float sum = 0.f;
#pragma unroll
    for (int k = lane; k < DH; k += 32) sum += er[k] * ws[k];
#pragma unroll
    for (int o = 16; o; o >>= 1) sum += __shfl_xor_sync(0xffffffffu, sum, o);
    if (lane == 0) g_s[row] = sum + g_cn[n];
}

extern "C" void kernel_launch(void* const* d_in, const int* in_sizes, int n_in,
                              void* d_out, int out_size)
{
    const float* x    = (const float*)d_in[0];
    const int*   task = (const int*)  d_in[1];
    const float* Wb1  = (const float*)d_in[2];
    const float* bb1  = (const float*)d_in[3];
    const float* Wb2  = (const float*)d_in[4];
    const float* bb2  = (const float*)d_in[5];
    const float* We1  = (const float*)d_in[6];
    const float* be1  = (const float*)d_in[7];
    const float* We2  = (const float*)d_in[8];
    const float* be2  = (const float*)d_in[9];
    const float* Wv   = (const float*)d_in[10];
    const float* bv   = (const float*)d_in[11];
    const float* Wk   = (const float*)d_in[12];
    const float* bk   = (const float*)d_in[13];
    const float* Wq   = (const float*)d_in[14];
    const float* bq   = (const float*)d_in[15];
    const float* Wt1  = (const float*)d_in[16];
    const float* bt1  = (const float*)d_in[17];
    const float* Wl   = (const float*)d_in[18];
    const float* bl   = (const float*)d_in[19];
    float* out = (float*)d_out;

    float *h1, *h, *e1, *e2, *res, *t, *sc;
    cudaGetSymbolAddress((void**)&h1,  g_h1);
    cudaGetSymbolAddress((void**)&h,   g_h);
    cudaGetSymbolAddress((void**)&e1,  g_e1);
    cudaGetSymbolAddress((void**)&e2,  g_e2);
    cudaGetSymbolAddress((void**)&res, g_res);
    cudaGetSymbolAddress((void**)&t,   g_t);
    cudaGetSymbolAddress((void**)&sc,  g_s);

    dim3 blk(256);
    dim3 gDH(DH / BN, BATCH / BM);     // (8, 32)
    dim3 gOUT(NOUT / BN, BATCH / BM);  // (1, 32)

    // base MLP
    gemm_k<EPI_RELU><<<gDH, blk>>>(x,  Wb1, bb1, h1, BATCH, DH, OBSD, nullptr, 0);
    gemm_k<EPI_RELU><<<gDH, blk>>>(h1, Wb2, bb2, h,  BATCH, DH, DH,   nullptr, 0);

    // q / wn / cn precompute
    prep_k<<<1, 256>>>(Wq, bq, bk, task);
    wn_k<<<(NEXP * DH) / 256, 256>>>(Wk);

    // experts
    for (int n = 0; n < NEXP; n++) {
        gemm_k<EPI_RELU><<<gDH, blk>>>(h,  We1 + (size_t)n * DH * DH, be1 + (size_t)n * DH,
                                       e1, BATCH, DH, DH, nullptr, 0);
        gemm_k<EPI_RELU><<<gDH, blk>>>(e1, We2 + (size_t)n * DH * DH, be2 + (size_t)n * DH,
                                       e2, BATCH, DH, DH, nullptr, 0);
        expkq_k<<<BATCH / 8, 256>>>(e2, n);
        gemm_k<EPI_SCALE><<<gDH, blk>>>(e2, Wv + (size_t)n * DH * DVV, bv + (size_t)n * DVV,
                                        res, BATCH, DVV, DH, sc, n > 0 ? 1 : 0);
    }

    // tower + head
    gemm_k<EPI_RELU ><<<gDH,  blk>>>(res, Wt1, bt1, t,   BATCH, DH,   DVV, nullptr, 0);
    gemm_k<EPI_SPLIT><<<gOUT, blk>>>(t,   Wl,  bl,  out, BATCH, NOUT, DH,  nullptr, 0);
}

// round 3
// speedup vs baseline: 2.2448x; 2.2448x over previous
#include <cuda_runtime.h>
#include <cuda_bf16.h>
#include <math.h>
#include <stdint.h>

#define BATCH  4096
#define OBSD   512
#define DH     1024
#define NEXP   8
#define DKK    256
#define DVV    1024
#define NTASKS 10
#define NOUT   128

// ------------------------- scratch (device globals) ------------------------
__device__ __nv_bfloat16 g_xh [BATCH*OBSD], g_xl [BATCH*OBSD];
__device__ __nv_bfloat16 g_h1h[BATCH*DH],   g_h1l[BATCH*DH];
__device__ __nv_bfloat16 g_hh [BATCH*DH],   g_hl [BATCH*DH];
__device__ __nv_bfloat16 g_e1h[BATCH*DH],   g_e1l[BATCH*DH];
__device__ __nv_bfloat16 g_e2h[BATCH*DH],   g_e2l[BATCH*DH];
__device__ float         g_res[BATCH*DVV];
__device__ __nv_bfloat16 g_rh [BATCH*DVV],  g_rl [BATCH*DVV];
__device__ __nv_bfloat16 g_th [BATCH*DH],   g_tl [BATCH*DH];

__device__ __nv_bfloat16 g_Wb1h[DH*OBSD],     g_Wb1l[DH*OBSD];
__device__ __nv_bfloat16 g_Wb2h[DH*DH],       g_Wb2l[DH*DH];
__device__ __nv_bfloat16 g_We1h[NEXP*DH*DH],  g_We1l[NEXP*DH*DH];
__device__ __nv_bfloat16 g_We2h[NEXP*DH*DH],  g_We2l[NEXP*DH*DH];
__device__ __nv_bfloat16 g_Wvh [NEXP*DH*DVV], g_Wvl [NEXP*DH*DVV];
__device__ __nv_bfloat16 g_Wt1h[DH*DVV],      g_Wt1l[DH*DVV];
__device__ __nv_bfloat16 g_Wlh [NOUT*DH],     g_Wll [NOUT*DH];

__device__ float g_q[DKK], g_wn[NEXP*DH], g_cn[NEXP], g_s[BATCH];

// ------------------------- PTX helpers -------------------------------------
__device__ __forceinline__ uint32_t smem_u32(const void* p) {
    uint32_t a;
    asm("{ .reg .u64 t; cvta.to.shared.u64 t, %1; cvt.u32.u64 %0, t; }" : "=r"(a) : "l"(p));
    return a;
}
__device__ __forceinline__ void cpa16(uint32_t dst, const void* src) {
    asm volatile("cp.async.cg.shared.global [%0], [%1], 16;" :: "r"(dst), "l"(src));
}
#define CP_COMMIT() asm volatile("cp.async.commit_group;" ::: "memory")
#define CP_WAIT0()  asm volatile("cp.async.wait_group 0;" ::: "memory")
#define CP_WAIT1()  asm volatile("cp.async.wait_group 1;" ::: "memory")

#define LDSM4(r0, r1, r2, r3, addr) \
    asm volatile("ldmatrix.sync.aligned.m8n8.x4.shared.b16 {%0,%1,%2,%3}, [%4];" \
                 : "=r"(r0), "=r"(r1), "=r"(r2), "=r"(r3) : "r"(addr))

#define MMA_BF16(d, a, b0v, b1v) \
    asm volatile("mma.sync.aligned.m16n8k16.row.col.f32.bf16.bf16.f32 " \
                 "{%0,%1,%2,%3},{%4,%5,%6,%7},{%8,%9},{%0,%1,%2,%3};" \
                 : "+f"((d)[0]), "+f"((d)[1]), "+f"((d)[2]), "+f"((d)[3]) \
                 : "r"((a)[0]), "r"((a)[1]), "r"((a)[2]), "r"((a)[3]), \
                   "r"(b0v), "r"(b1v))

// ------------------------- mma.sync bf16x3 GEMM -----------------------------
// C[M,N] = epi(A @ B^T + bias).  A = Ah+Al [M,K] bf16 row-major,
// B^T given as Bh/Bl [N,K] bf16 row-major.  CTA tile 128x128, BK=32.
enum { EPI_RELU = 0, EPI_SCALE = 1, EPI_SPLIT = 2 };

#define LDSR   40                         // smem row stride in elems (pad 8)
#define TILEB  (128 * LDSR * 2)           // bytes per sub-tile (Ah/Al/Bh/Bl)
#define STAGEB (4 * TILEB)                // bytes per pipeline stage

template <int EPI>
__global__ __launch_bounds__(256)
void mma_gemm(const __nv_bfloat16* __restrict__ Ah, const __nv_bfloat16* __restrict__ Al,
              const __nv_bfloat16* __restrict__ Bh, const __nv_bfloat16* __restrict__ Bl,
              const float* __restrict__ bias, int N, int K,
              float* __restrict__ Cf,
              __nv_bfloat16* __restrict__ Ch, __nv_bfloat16* __restrict__ Cl,
              const float* __restrict__ scale, int beta)
{
    extern __shared__ char smem[];
    const uint32_t sbuf = smem_u32(smem);
    const int tid = threadIdx.x, wid = tid >> 5, lane = tid & 31;
    const int m0 = blockIdx.y * 128, n0 = blockIdx.x * 128;
    const int warp_m = (wid >> 1) * 32;    // 4 warps in M
    const int warp_n = (wid & 1) * 64;     // 2 warps in N

    float acc[2][8][4];
#pragma unroll
    for (int a = 0; a < 2; a++)
#pragma unroll
        for (int b = 0; b < 8; b++)
#pragma unroll
            for (int c = 0; c < 4; c++) acc[a][b][c] = 0.f;

    const int KT = K >> 5;                 // chunks of 32

    auto load_stage = [&](int kt, int s) {
        const uint32_t base = sbuf + s * STAGEB;
        const int k0 = kt << 5;
#pragma unroll
        for (int part = 0; part < 4; part++) {
            const __nv_bfloat16* src =
                (part == 0 ? Ah : part == 1 ? Al : part == 2 ? Bh : Bl)
                + (size_t)(part < 2 ? m0 : n0) * K + k0;
            const uint32_t dstb = base + part * TILEB;
#pragma unroll
            for (int i = 0; i < 2; i++) {
                int idx = i * 256 + tid;          // 512 granules of 16B
                int row = idx >> 2, gc = idx & 3;
                cpa16(dstb + (uint32_t)(row * LDSR + gc * 8) * 2,
                      src + (size_t)row * K + gc * 8);
            }
        }
        CP_COMMIT();
    };

    load_stage(0, 0);
    load_stage(1, 1);

    for (int kt = 0; kt < KT; kt++) {
        const int s = kt & 1;
        if (kt == KT - 1) { CP_WAIT0(); } else { CP_WAIT1(); }
        __syncthreads();

        const uint32_t base = sbuf + s * STAGEB;
#pragma unroll
        for (int kk = 0; kk < 2; kk++) {
            const int ko = kk * 16;
            uint32_t ah[2][4], al[2][4];
#pragma unroll
            for (int mt = 0; mt < 2; mt++) {
                const uint32_t arow = warp_m + mt * 16 + ((lane >> 3) & 1) * 8 + (lane & 7);
                const uint32_t acol = ko + (lane >> 4) * 8;
                const uint32_t ad = base + (arow * LDSR + acol) * 2;
                LDSM4(ah[mt][0], ah[mt][1], ah[mt][2], ah[mt][3], ad);
                LDSM4(al[mt][0], al[mt][1], al[mt][2], al[mt][3], ad + TILEB);
            }
#pragma unroll
            for (int np = 0; np < 4; np++) {
                const uint32_t nrow = warp_n + np * 16 + ((lane >> 4) & 1) * 8 + (lane & 7);
                const uint32_t kcol = ko + ((lane >> 3) & 1) * 8;
                const uint32_t bd = base + 2 * TILEB + (nrow * LDSR + kcol) * 2;
                uint32_t bh[4], bl[4];
                LDSM4(bh[0], bh[1], bh[2], bh[3], bd);
                LDSM4(bl[0], bl[1], bl[2], bl[3], bd + TILEB);
#pragma unroll
                for (int mt = 0; mt < 2; mt++) {
                    MMA_BF16(acc[mt][np * 2],     ah[mt], bh[0], bh[1]);
                    MMA_BF16(acc[mt][np * 2],     ah[mt], bl[0], bl[1]);
                    MMA_BF16(acc[mt][np * 2],     al[mt], bh[0], bh[1]);
                    MMA_BF16(acc[mt][np * 2 + 1], ah[mt], bh[2], bh[3]);
                    MMA_BF16(acc[mt][np * 2 + 1], ah[mt], bl[2], bl[3]);
                    MMA_BF16(acc[mt][np * 2 + 1], al[mt], bh[2], bh[3]);
                }
            }
        }
        __syncthreads();
        if (kt + 2 < KT) load_stage(kt + 2, s);
    }

    // ------------- epilogue -------------
    const int tr = lane >> 2, tc = (lane & 3) * 2;
#pragma unroll
    for (int mt = 0; mt < 2; mt++) {
#pragma unroll
        for (int half = 0; half < 2; half++) {     // c0/c1 vs c2/c3
            const int r = m0 + warp_m + mt * 16 + tr + half * 8;
#pragma unroll
            for (int j = 0; j < 8; j++) {
                const int col = n0 + warp_n + j * 8 + tc;
                float v0 = acc[mt][j][half * 2]     + bias[col];
                float v1 = acc[mt][j][half * 2 + 1] + bias[col + 1];

                if (EPI == EPI_RELU) {
                    v0 = fmaxf(v0, 0.f); v1 = fmaxf(v1, 0.f);
                    __nv_bfloat16 h0 = __float2bfloat16_rn(v0);
                    __nv_bfloat16 h1 = __float2bfloat16_rn(v1);
                    __nv_bfloat16 l0 = __float2bfloat16_rn(v0 - __bfloat162float(h0));
                    __nv_bfloat16 l1 = __float2bfloat16_rn(v1 - __bfloat162float(h1));
                    *(__nv_bfloat162*)(Ch + (size_t)r * N + col) = __halves2bfloat162(h0, h1);
                    *(__nv_bfloat162*)(Cl + (size_t)r * N + col) = __halves2bfloat162(l0, l1);
                } else if (EPI == EPI_SCALE) {
                    const float sv = scale[r];
                    float* dst = Cf + (size_t)r * N + col;
                    float2 o = beta ? *(float2*)dst : make_float2(0.f, 0.f);
                    o.x += v0 * sv; o.y += v1 * sv;
                    *(float2*)dst = o;
                } else {   // EPI_SPLIT: out = [mean | std | log_std], each [B,64]
                    if (col < 64) {
                        Cf[(size_t)r * 64 + col]     = v0;
                        Cf[(size_t)r * 64 + col + 1] = v1;
                    } else {
                        float l0 = fminf(fmaxf(v0, -20.f), 2.f);
                        float l1 = fminf(fmaxf(v1, -20.f), 2.f);
                        Cf[(size_t)BATCH * 64 + (size_t)r * 64 + (col - 64)]     = expf(l0);
                        Cf[(size_t)BATCH * 64 + (size_t)r * 64 + (col - 63)]     = expf(l1);
                        Cf[(size_t)2 * BATCH * 64 + (size_t)r * 64 + (col - 64)] = l0;
                        Cf[(size_t)2 * BATCH * 64 + (size_t)r * 64 + (col - 63)] = l1;
                    }
                }
            }
        }
    }
}

// ------------------------- prep kernels ------------------------------------
// W[K,N] fp32 -> Th/Tl[N,K] bf16 (transpose + hi/lo split)
__global__ void transpose_split_k(const float* __restrict__ W,
                                  __nv_bfloat16* __restrict__ Th,
                                  __nv_bfloat16* __restrict__ Tl, int K, int N)
{
    __shared__ float tile[32][33];
    const size_t moff = (size_t)blockIdx.z * K * N;
    const float* Wb = W + moff;
    const int k0 = blockIdx.x * 32, n0 = blockIdx.y * 32;
    const int tx = threadIdx.x, ty = threadIdx.y;
#pragma unroll
    for (int i = ty; i < 32; i += 8)
        tile[i][tx] = Wb[(size_t)(k0 + i) * N + n0 + tx];
    __syncthreads();
#pragma unroll
    for (int i = ty; i < 32; i += 8) {
        float v = tile[tx][i];
        __nv_bfloat16 h = __float2bfloat16_rn(v);
        __nv_bfloat16 l = __float2bfloat16_rn(v - __bfloat162float(h));
        size_t o = moff + (size_t)(n0 + i) * K + k0 + tx;
        Th[o] = h; Tl[o] = l;
    }
}

__global__ void split_k(const float* __restrict__ X, __nv_bfloat16* __restrict__ Xh,
                        __nv_bfloat16* __restrict__ Xl, int n)
{
    int i = blockIdx.x * 256 + threadIdx.x;
    if (i < n) {
        float v = X[i];
        __nv_bfloat16 h = __float2bfloat16_rn(v);
        Xh[i] = h;
        Xl[i] = __float2bfloat16_rn(v - __bfloat162float(h));
    }
}

// q = Wq[t][t,:] + bq[t];  cn[n] = dot(bk[n], q)
__global__ void prep_k(const float* __restrict__ Wq, const float* __restrict__ bq,
                       const float* __restrict__ bk, const int* __restrict__ task_id)
{
    __shared__ float qs[DKK];
    const int t = *task_id;
    const int tid = threadIdx.x;
    float qv = Wq[(size_t)(t * NTASKS + t) * DKK + tid] + bq[(size_t)t * DKK + tid];
    g_q[tid] = qv;
    qs[tid]  = qv;
    __syncthreads();
    const int w = tid >> 5, lane = tid & 31;
    float sum = 0.f;
#pragma unroll
    for (int k = lane; k < DKK; k += 32) sum += bk[(size_t)w * DKK + k] * qs[k];
#pragma unroll
    for (int o = 16; o; o >>= 1) sum += __shfl_xor_sync(0xffffffffu, sum, o);
    if (lane == 0) g_cn[w] = sum;
}

// wn[i] = dot(Wk[i,:], q)   (warp per row)
__global__ void wn_k(const float* __restrict__ Wk)
{
    const int tid = threadIdx.x, w = tid >> 5, lane = tid & 31;
    const int row = blockIdx.x * 8 + w;
    const float* wr = Wk + (size_t)row * DKK;
    float sum = 0.f;
#pragma unroll
    for (int k = lane; k < DKK; k += 32) sum += wr[k] * g_q[k];
#pragma unroll
    for (int o = 16; o; o >>= 1) sum += __shfl_xor_sync(0xffffffffu, sum, o);
    if (lane == 0) g_wn[row] = sum;
}

// s[b] = dot(e2h+e2l, wn[n]) + cn[n]   (warp per row)
__global__ void expkq_k(int n)
{
    const int tid = threadIdx.x, w = tid >> 5, lane = tid & 31;
    const int row = blockIdx.x * 8 + w;
    const __nv_bfloat16* eh = g_e2h + (size_t)row * DH;
    const __nv_bfloat16* el = g_e2l + (size_t)row * DH;
    const float* wn = g_wn + (size_t)n * DH;
    float sum = 0.f;
#pragma unroll 4
    for (int k = lane; k < DH; k += 32)
        sum += (__bfloat162float(eh[k]) + __bfloat162float(el[k])) * wn[k];
#pragma unroll
    for (int o = 16; o; o >>= 1) sum += __shfl_xor_sync(0xffffffffu, sum, o);
    if (lane == 0) g_s[row] = sum + g_cn[n];
}

// ------------------------- launch ------------------------------------------
extern "C" void kernel_launch(void* const* d_in, const int* in_sizes, int n_in,
                              void* d_out, int out_size)
{
    const float* x    = (const float*)d_in[0];
    const int*   task = (const int*)  d_in[1];
    const float* Wb1  = (const float*)d_in[2];
    const float* bb1  = (const float*)d_in[3];
    const float* Wb2  = (const float*)d_in[4];
    const float* bb2  = (const float*)d_in[5];
    const float* We1  = (const float*)d_in[6];
    const float* be1  = (const float*)d_in[7];
    const float* We2  = (const float*)d_in[8];
    const float* be2  = (const float*)d_in[9];
    const float* Wv   = (const float*)d_in[10];
    const float* bv   = (const float*)d_in[11];
    const float* Wk   = (const float*)d_in[12];
    const float* bk   = (const float*)d_in[13];
    const float* Wq   = (const float*)d_in[14];
    const float* bq   = (const float*)d_in[15];
    const float* Wt1  = (const float*)d_in[16];
    const float* bt1  = (const float*)d_in[17];
    const float* Wl   = (const float*)d_in[18];
    const float* bl   = (const float*)d_in[19];
    float* out = (float*)d_out;

#define SYM(p, s) do { void* _t; cudaGetSymbolAddress(&_t, s); p = (decltype(p))_t; } while (0)
    __nv_bfloat16 *xh, *xl, *h1h, *h1l, *hh, *hl, *e1h, *e1l, *e2h, *e2l;
    __nv_bfloat16 *rh, *rl, *th, *tl;
    __nv_bfloat16 *Wb1h, *Wb1l, *Wb2h, *Wb2l, *We1h, *We1l, *We2h, *We2l;
    __nv_bfloat16 *Wvh, *Wvl, *Wt1h, *Wt1l, *Wlh, *Wll;
    float *res, *sc;
    SYM(xh, g_xh);  SYM(xl, g_xl);  SYM(h1h, g_h1h); SYM(h1l, g_h1l);
    SYM(hh, g_hh);  SYM(hl, g_hl);  SYM(e1h, g_e1h); SYM(e1l, g_e1l);
    SYM(e2h, g_e2h); SYM(e2l, g_e2l); SYM(res, g_res);
    SYM(rh, g_rh);  SYM(rl, g_rl);  SYM(th, g_th);  SYM(tl, g_tl);
    SYM(Wb1h, g_Wb1h); SYM(Wb1l, g_Wb1l); SYM(Wb2h, g_Wb2h); SYM(Wb2l, g_Wb2l);
    SYM(We1h, g_We1h); SYM(We1l, g_We1l); SYM(We2h, g_We2h); SYM(We2l, g_We2l);
    SYM(Wvh, g_Wvh); SYM(Wvl, g_Wvl); SYM(Wt1h, g_Wt1h); SYM(Wt1l, g_Wt1l);
    SYM(Wlh, g_Wlh); SYM(Wll, g_Wll); SYM(sc, g_s);

    const int SMEM = 2 * STAGEB;   // 81920
    cudaFuncSetAttribute(mma_gemm<EPI_RELU >, cudaFuncAttributeMaxDynamicSharedMemorySize, SMEM);
    cudaFuncSetAttribute(mma_gemm<EPI_SCALE>, cudaFuncAttributeMaxDynamicSharedMemorySize, SMEM);
    cudaFuncSetAttribute(mma_gemm<EPI_SPLIT>, cudaFuncAttributeMaxDynamicSharedMemorySize, SMEM);

    dim3 tb(32, 8);
    transpose_split_k<<<dim3(OBSD / 32, DH / 32, 1),   tb>>>(Wb1, Wb1h, Wb1l, OBSD, DH);
    transpose_split_k<<<dim3(DH / 32, DH / 32, 1),     tb>>>(Wb2, Wb2h, Wb2l, DH, DH);
    transpose_split_k<<<dim3(DH / 32, DH / 32, NEXP),  tb>>>(We1, We1h, We1l, DH, DH);
    transpose_split_k<<<dim3(DH / 32, DH / 32, NEXP),  tb>>>(We2, We2h, We2l, DH, DH);
    transpose_split_k<<<dim3(DH / 32, DVV / 32, NEXP), tb>>>(Wv, Wvh, Wvl, DH, DVV);
    transpose_split_k<<<dim3(DVV / 32, DH / 32, 1),    tb>>>(Wt1, Wt1h, Wt1l, DVV, DH);
    transpose_split_k<<<dim3(DH / 32, NOUT / 32, 1),   tb>>>(Wl, Wlh, Wll, DH, NOUT);

    split_k<<<(BATCH * OBSD + 255) / 256, 256>>>(x, xh, xl, BATCH * OBSD);

    prep_k<<<1, 256>>>(Wq, bq, bk, task);
    wn_k<<<NEXP * DH / 8, 256>>>(Wk);

    const dim3 gDH(DH / 128, BATCH / 128);     // (8, 32)
    const dim3 gout(1, BATCH / 128);

    mma_gemm<EPI_RELU><<<gDH, 256, SMEM>>>(xh, xl, Wb1h, Wb1l, bb1, DH, OBSD,
                                           nullptr, h1h, h1l, nullptr, 0);
    mma_gemm<EPI_RELU><<<gDH, 256, SMEM>>>(h1h, h1l, Wb2h, Wb2l, bb2, DH, DH,
                                           nullptr, hh, hl, nullptr, 0);
    for (int n = 0; n < NEXP; n++) {
        mma_gemm<EPI_RELU><<<gDH, 256, SMEM>>>(
            hh, hl, We1h + (size_t)n * DH * DH, We1l + (size_t)n * DH * DH,
            be1 + (size_t)n * DH, DH, DH, nullptr, e1h, e1l, nullptr, 0);
        mma_gemm<EPI_RELU><<<gDH, 256, SMEM>>>(
            e1h, e1l, We2h + (size_t)n * DH * DH, We2l + (size_t)n * DH * DH,
            be2 + (size_t)n * DH, DH, DH, nullptr, e2h, e2l, nullptr, 0);
        expkq_k<<<BATCH / 8, 256>>>(n);
        mma_gemm<EPI_SCALE><<<gDH, 256, SMEM>>>(
            e2h, e2l, Wvh + (size_t)n * DH * DVV, Wvl + (size_t)n * DH * DVV,
            bv + (size_t)n * DVV, DVV, DH, res, nullptr, nullptr, sc, n > 0 ? 1 : 0);
    }
    split_k<<<(BATCH * DVV + 255) / 256, 256>>>(res, rh, rl, BATCH * DVV);
    mma_gemm<EPI_RELU><<<gDH, 256, SMEM>>>(rh, rl, Wt1h, Wt1l, bt1, DH, DVV,
                                           nullptr, th, tl, nullptr, 0);
    mma_gemm<EPI_SPLIT><<<gout, 256, SMEM>>>(th, tl, Wlh, Wll, bl, NOUT, DH,
                                             out, nullptr, nullptr, nullptr, 0);
}

// round 4
// speedup vs baseline: 2.8020x; 1.2482x over previous
#include <cuda_runtime.h>
#include <cuda_bf16.h>
#include <math.h>
#include <stdint.h>

#define BATCH  4096
#define OBSD   512
#define DH     1024
#define NEXP   8
#define DKK    256
#define DVV    1024
#define NTASKS 10
#define NOUT   128
#define NDH8   (NEXP * DH)          // 8192

// ------------------------- scratch (device globals) ------------------------
__device__ __nv_bfloat16 g_xh [BATCH*OBSD], g_xl [BATCH*OBSD];
__device__ __nv_bfloat16 g_h1h[BATCH*DH],   g_h1l[BATCH*DH];
__device__ __nv_bfloat16 g_hh [BATCH*DH],   g_hl [BATCH*DH];
__device__ __nv_bfloat16 g_e1h[(size_t)BATCH*NDH8], g_e1l[(size_t)BATCH*NDH8];
__device__ __nv_bfloat16 g_e2h[(size_t)BATCH*NDH8], g_e2l[(size_t)BATCH*NDH8];
__device__ __nv_bfloat16 g_vth[(size_t)BATCH*NDH8], g_vtl[(size_t)BATCH*NDH8];
__device__ __nv_bfloat16 g_rh [BATCH*DVV],  g_rl [BATCH*DVV];
__device__ __nv_bfloat16 g_th [BATCH*DH],   g_tl [BATCH*DH];

__device__ __nv_bfloat16 g_Wb1h[DH*OBSD],     g_Wb1l[DH*OBSD];
__device__ __nv_bfloat16 g_Wb2h[DH*DH],       g_Wb2l[DH*DH];
__device__ __nv_bfloat16 g_We1h[NEXP*DH*DH],  g_We1l[NEXP*DH*DH];
__device__ __nv_bfloat16 g_We2h[NEXP*DH*DH],  g_We2l[NEXP*DH*DH];
__device__ __nv_bfloat16 g_Wvh [(size_t)DVV*NDH8], g_Wvl [(size_t)DVV*NDH8];
__device__ __nv_bfloat16 g_Wt1h[DH*DVV],      g_Wt1l[DH*DVV];
__device__ __nv_bfloat16 g_Wlh [NOUT*DH],     g_Wll [NOUT*DH];

__device__ float g_q[DKK], g_wn[NEXP*DH], g_cn[NEXP], g_s[NEXP*BATCH];

// ------------------------- PTX helpers -------------------------------------
__device__ __forceinline__ uint32_t smem_u32(const void* p) {
    uint32_t a;
    asm("{ .reg .u64 t; cvta.to.shared.u64 t, %1; cvt.u32.u64 %0, t; }" : "=r"(a) : "l"(p));
    return a;
}
__device__ __forceinline__ void cpa16(uint32_t dst, const void* src) {
    asm volatile("cp.async.cg.shared.global [%0], [%1], 16;" :: "r"(dst), "l"(src));
}
#define CP_COMMIT() asm volatile("cp.async.commit_group;" ::: "memory")
#define CP_WAIT0()  asm volatile("cp.async.wait_group 0;" ::: "memory")
#define CP_WAIT1()  asm volatile("cp.async.wait_group 1;" ::: "memory")

#define LDSM4(r0, r1, r2, r3, addr) \
    asm volatile("ldmatrix.sync.aligned.m8n8.x4.shared.b16 {%0,%1,%2,%3}, [%4];" \
                 : "=r"(r0), "=r"(r1), "=r"(r2), "=r"(r3) : "r"(addr))

#define MMA_BF16(d, a, b0v, b1v) \
    asm volatile("mma.sync.aligned.m16n8k16.row.col.f32.bf16.bf16.f32 " \
                 "{%0,%1,%2,%3},{%4,%5,%6,%7},{%8,%9},{%0,%1,%2,%3};" \
                 : "+f"((d)[0]), "+f"((d)[1]), "+f"((d)[2]), "+f"((d)[3]) \
                 : "r"((a)[0]), "r"((a)[1]), "r"((a)[2]), "r"((a)[3]), \
                   "r"(b0v), "r"(b1v))

// ------------------------- mma.sync bf16x3 GEMM -----------------------------
// C[:, coffz*z + n0..] = epi(A[:, aoffz*z + :K] @ B^T + bias)
// A = Ah+Al row-major (stride lda);  B rows (N-dim) K-major (stride ldb).
enum { EPI_RELU = 0, EPI_VSUM = 1, EPI_SPLIT = 2 };

#define LDSR   40                         // smem row stride in elems (pad 8)
#define TILEB  (128 * LDSR * 2)           // bytes per sub-tile
#define STAGEB (4 * TILEB)

template <int EPI>
__global__ __launch_bounds__(256, 2)
void mma_gemm(const __nv_bfloat16* __restrict__ Ah, const __nv_bfloat16* __restrict__ Al,
              int lda, int aoffz,
              const __nv_bfloat16* __restrict__ Bh, const __nv_bfloat16* __restrict__ Bl,
              int ldb, int boffz,
              const float* __restrict__ bias, int biasoffz,
              int K,
              float* __restrict__ Cf,
              __nv_bfloat16* __restrict__ Ch, __nv_bfloat16* __restrict__ Cl,
              int ldc, int coffz,
              const float* __restrict__ sarr, const float* __restrict__ bvv)
{
    extern __shared__ char smem[];
    const uint32_t sbuf = smem_u32(smem);
    const int tid = threadIdx.x, wid = tid >> 5, lane = tid & 31;
    const int z = blockIdx.z;
    const int m0 = blockIdx.y * 128, n0 = blockIdx.x * 128;
    const int warp_m = (wid >> 1) * 32;
    const int warp_n = (wid & 1) * 64;

    const __nv_bfloat16* Abase_h = Ah + (size_t)m0 * lda + (size_t)z * aoffz;
    const __nv_bfloat16* Abase_l = Al + (size_t)m0 * lda + (size_t)z * aoffz;
    const __nv_bfloat16* Bbase_h = Bh + (size_t)z * boffz + (size_t)n0 * ldb;
    const __nv_bfloat16* Bbase_l = Bl + (size_t)z * boffz + (size_t)n0 * ldb;

    float acc[2][8][4];
#pragma unroll
    for (int a = 0; a < 2; a++)
#pragma unroll
        for (int b = 0; b < 8; b++)
#pragma unroll
            for (int c = 0; c < 4; c++) acc[a][b][c] = 0.f;

    const int KT = K >> 5;

    auto load_stage = [&](int kt, int s) {
        const uint32_t base = sbuf + s * STAGEB;
        const int k0 = kt << 5;
#pragma unroll
        for (int part = 0; part < 4; part++) {
            const __nv_bfloat16* src =
                (part == 0 ? Abase_h : part == 1 ? Abase_l : part == 2 ? Bbase_h : Bbase_l);
            const int ld = (part < 2) ? lda : ldb;
            const uint32_t dstb = base + part * TILEB;
#pragma unroll
            for (int i = 0; i < 2; i++) {
                int idx = i * 256 + tid;
                int row = idx >> 2, gc = idx & 3;
                cpa16(dstb + (uint32_t)(row * LDSR + gc * 8) * 2,
                      src + (size_t)row * ld + k0 + gc * 8);
            }
        }
        CP_COMMIT();
    };

    load_stage(0, 0);
    load_stage(1, 1);

    for (int kt = 0; kt < KT; kt++) {
        const int s = kt & 1;
        if (kt == KT - 1) { CP_WAIT0(); } else { CP_WAIT1(); }
        __syncthreads();

        const uint32_t base = sbuf + s * STAGEB;
#pragma unroll
        for (int kk = 0; kk < 2; kk++) {
            const int ko = kk * 16;
            uint32_t ah[2][4], al[2][4];
#pragma unroll
            for (int mt = 0; mt < 2; mt++) {
                const uint32_t arow = warp_m + mt * 16 + ((lane >> 3) & 1) * 8 + (lane & 7);
                const uint32_t acol = ko + (lane >> 4) * 8;
                const uint32_t ad = base + (arow * LDSR + acol) * 2;
                LDSM4(ah[mt][0], ah[mt][1], ah[mt][2], ah[mt][3], ad);
                LDSM4(al[mt][0], al[mt][1], al[mt][2], al[mt][3], ad + TILEB);
            }
#pragma unroll
            for (int npg = 0; npg < 2; npg++) {
                uint32_t bh[2][4], bl[2][4];
#pragma unroll
                for (int p = 0; p < 2; p++) {
                    const int np = npg * 2 + p;
                    const uint32_t nrow = warp_n + np * 16 + ((lane >> 4) & 1) * 8 + (lane & 7);
                    const uint32_t kcol = ko + ((lane >> 3) & 1) * 8;
                    const uint32_t bd = base + 2 * TILEB + (nrow * LDSR + kcol) * 2;
                    LDSM4(bh[p][0], bh[p][1], bh[p][2], bh[p][3], bd);
                    LDSM4(bl[p][0], bl[p][1], bl[p][2], bl[p][3], bd + TILEB);
                }
                // pass 1: Ah x Bh   (8 independent MMAs)
#pragma unroll
                for (int p = 0; p < 2; p++)
#pragma unroll
                    for (int mt = 0; mt < 2; mt++) {
                        MMA_BF16(acc[mt][(npg * 2 + p) * 2],     ah[mt], bh[p][0], bh[p][1]);
                        MMA_BF16(acc[mt][(npg * 2 + p) * 2 + 1], ah[mt], bh[p][2], bh[p][3]);
                    }
                // pass 2: Ah x Bl
#pragma unroll
                for (int p = 0; p < 2; p++)
#pragma unroll
                    for (int mt = 0; mt < 2; mt++) {
                        MMA_BF16(acc[mt][(npg * 2 + p) * 2],     ah[mt], bl[p][0], bl[p][1]);
                        MMA_BF16(acc[mt][(npg * 2 + p) * 2 + 1], ah[mt], bl[p][2], bl[p][3]);
                    }
                // pass 3: Al x Bh
#pragma unroll
                for (int p = 0; p < 2; p++)
#pragma unroll
                    for (int mt = 0; mt < 2; mt++) {
                        MMA_BF16(acc[mt][(npg * 2 + p) * 2],     al[mt], bh[p][0], bh[p][1]);
                        MMA_BF16(acc[mt][(npg * 2 + p) * 2 + 1], al[mt], bh[p][2], bh[p][3]);
                    }
            }
        }
        __syncthreads();
        if (kt + 2 < KT) load_stage(kt + 2, s);
    }

    // ------------- epilogue -------------
    const int tr = lane >> 2, tc = (lane & 3) * 2;
#pragma unroll
    for (int mt = 0; mt < 2; mt++) {
#pragma unroll
        for (int half = 0; half < 2; half++) {
            const int r = m0 + warp_m + mt * 16 + tr + half * 8;
            float sv8[NEXP];
            if (EPI == EPI_VSUM) {
#pragma unroll
                for (int n = 0; n < NEXP; n++) sv8[n] = sarr[n * BATCH + r];
            }
#pragma unroll
            for (int j = 0; j < 8; j++) {
                const int col = n0 + warp_n + j * 8 + tc;
                float v0 = acc[mt][j][half * 2];
                float v1 = acc[mt][j][half * 2 + 1];

                if (EPI == EPI_RELU) {
                    v0 += bias[(size_t)z * biasoffz + col];
                    v1 += bias[(size_t)z * biasoffz + col + 1];
                    v0 = fmaxf(v0, 0.f); v1 = fmaxf(v1, 0.f);
                    __nv_bfloat16 h0 = __float2bfloat16_rn(v0);
                    __nv_bfloat16 h1 = __float2bfloat16_rn(v1);
                    __nv_bfloat16 l0 = __float2bfloat16_rn(v0 - __bfloat162float(h0));
                    __nv_bfloat16 l1 = __float2bfloat16_rn(v1 - __bfloat162float(h1));
                    size_t o = (size_t)r * ldc + (size_t)z * coffz + col;
                    *(__nv_bfloat162*)(Ch + o) = __halves2bfloat162(h0, h1);
                    *(__nv_bfloat162*)(Cl + o) = __halves2bfloat162(l0, l1);
                } else if (EPI == EPI_VSUM) {
#pragma unroll
                    for (int n = 0; n < NEXP; n++) {
                        v0 += bvv[n * DVV + col]     * sv8[n];
                        v1 += bvv[n * DVV + col + 1] * sv8[n];
                    }
                    __nv_bfloat16 h0 = __float2bfloat16_rn(v0);
                    __nv_bfloat16 h1 = __float2bfloat16_rn(v1);
                    __nv_bfloat16 l0 = __float2bfloat16_rn(v0 - __bfloat162float(h0));
                    __nv_bfloat16 l1 = __float2bfloat16_rn(v1 - __bfloat162float(h1));
                    size_t o = (size_t)r * ldc + col;
                    *(__nv_bfloat162*)(Ch + o) = __halves2bfloat162(h0, h1);
                    *(__nv_bfloat162*)(Cl + o) = __halves2bfloat162(l0, l1);
                } else {   // EPI_SPLIT
                    v0 += bias[col]; v1 += bias[col + 1];
                    if (col < 64) {
                        Cf[(size_t)r * 64 + col]     = v0;
                        Cf[(size_t)r * 64 + col + 1] = v1;
                    } else {
                        float l0 = fminf(fmaxf(v0, -20.f), 2.f);
                        float l1 = fminf(fmaxf(v1, -20.f), 2.f);
                        Cf[(size_t)BATCH * 64 + (size_t)r * 64 + (col - 64)]     = expf(l0);
                        Cf[(size_t)BATCH * 64 + (size_t)r * 64 + (col - 63)]     = expf(l1);
                        Cf[(size_t)2 * BATCH * 64 + (size_t)r * 64 + (col - 64)] = l0;
                        Cf[(size_t)2 * BATCH * 64 + (size_t)r * 64 + (col - 63)] = l1;
                    }
                }
            }
        }
    }
}

// ------------------------- prep kernels ------------------------------------
// per z: W[K,N] fp32 -> out[(n0+i)*ors + z*zoff + k]  (transpose + hi/lo split)
__global__ void transpose_split_k(const float* __restrict__ W,
                                  __nv_bfloat16* __restrict__ Th,
                                  __nv_bfloat16* __restrict__ Tl,
                                  int K, int N, int ors, size_t zoff)
{
    __shared__ float tile[32][33];
    const int z = blockIdx.z;
    const float* Wb = W + (size_t)z * K * N;
    const int k0 = blockIdx.x * 32, n0 = blockIdx.y * 32;
    const int tx = threadIdx.x, ty = threadIdx.y;
#pragma unroll
    for (int i = ty; i < 32; i += 8)
        tile[i][tx] = Wb[(size_t)(k0 + i) * N + n0 + tx];
    __syncthreads();
#pragma unroll
    for (int i = ty; i < 32; i += 8) {
        float v = tile[tx][i];
        __nv_bfloat16 h = __float2bfloat16_rn(v);
        __nv_bfloat16 l = __float2bfloat16_rn(v - __bfloat162float(h));
        size_t o = (size_t)z * zoff + (size_t)(n0 + i) * ors + k0 + tx;
        Th[o] = h; Tl[o] = l;
    }
}

__global__ void split_k(const float* __restrict__ X, __nv_bfloat16* __restrict__ Xh,
                        __nv_bfloat16* __restrict__ Xl, int n)
{
    int i = blockIdx.x * 256 + threadIdx.x;
    if (i < n) {
        float v = X[i];
        __nv_bfloat16 h = __float2bfloat16_rn(v);
        Xh[i] = h;
        Xl[i] = __float2bfloat16_rn(v - __bfloat162float(h));
    }
}

// q = Wq[t][t,:] + bq[t];  cn[n] = dot(bk[n], q)
__global__ void prep_k(const float* __restrict__ Wq, const float* __restrict__ bq,
                       const float* __restrict__ bk, const int* __restrict__ task_id)
{
    __shared__ float qs[DKK];
    const int t = *task_id;
    const int tid = threadIdx.x;
    float qv = Wq[(size_t)(t * NTASKS + t) * DKK + tid] + bq[(size_t)t * DKK + tid];
    g_q[tid] = qv;
    qs[tid]  = qv;
    __syncthreads();
    const int w = tid >> 5, lane = tid & 31;
    float sum = 0.f;
#pragma unroll
    for (int k = lane; k < DKK; k += 32) sum += bk[(size_t)w * DKK + k] * qs[k];
#pragma unroll
    for (int o = 16; o; o >>= 1) sum += __shfl_xor_sync(0xffffffffu, sum, o);
    if (lane == 0) g_cn[w] = sum;
}

// wn[i] = dot(Wk[i,:], q)
__global__ void wn_k(const float* __restrict__ Wk)
{
    const int tid = threadIdx.x, w = tid >> 5, lane = tid & 31;
    const int row = blockIdx.x * 8 + w;
    const float* wr = Wk + (size_t)row * DKK;
    float sum = 0.f;
#pragma unroll
    for (int k = lane; k < DKK; k += 32) sum += wr[k] * g_q[k];
#pragma unroll
    for (int o = 16; o; o >>= 1) sum += __shfl_xor_sync(0xffffffffu, sum, o);
    if (lane == 0) g_wn[row] = sum;
}

// s[n][b] = dot(e2[b, n*DH..], wn[n]) + cn[n]
__global__ void expkq_k()
{
    const int tid = threadIdx.x, w = tid >> 5, lane = tid & 31;
    const int row = blockIdx.x * 8 + w;
    const int n = blockIdx.y;
    const size_t base = (size_t)row * NDH8 + (size_t)n * DH;
    const float* wn = g_wn + n * DH;
    float sum = 0.f;
#pragma unroll 4
    for (int it = 0; it < DH / 64; it++) {
        int k = it * 64 + lane * 2;
        __nv_bfloat162 h2 = *(const __nv_bfloat162*)(g_e2h + base + k);
        __nv_bfloat162 l2 = *(const __nv_bfloat162*)(g_e2l + base + k);
        sum += (__bfloat162float(h2.x) + __bfloat162float(l2.x)) * wn[k];
        sum += (__bfloat162float(h2.y) + __bfloat162float(l2.y)) * wn[k + 1];
    }
#pragma unroll
    for (int o = 16; o; o >>= 1) sum += __shfl_xor_sync(0xffffffffu, sum, o);
    if (lane == 0) g_s[n * BATCH + row] = sum + g_cn[n];
}

// vt[b, n*DH+d] = split( (e2h+e2l)[b,n*DH+d] * s[n][b] )
__global__ void scale_split_k()
{
    const size_t i0 = ((size_t)blockIdx.x * 256 + threadIdx.x) * 8;
    const int b = (int)(i0 / NDH8);
    const int c = (int)(i0 % NDH8);
    const int n = c >> 10;
    const float s = g_s[n * BATCH + b];
#pragma unroll
    for (int p = 0; p < 4; p++) {
        __nv_bfloat162 h2 = *(const __nv_bfloat162*)(g_e2h + i0 + p * 2);
        __nv_bfloat162 l2 = *(const __nv_bfloat162*)(g_e2l + i0 + p * 2);
        float v0 = (__bfloat162float(h2.x) + __bfloat162float(l2.x)) * s;
        float v1 = (__bfloat162float(h2.y) + __bfloat162float(l2.y)) * s;
        __nv_bfloat16 hh0 = __float2bfloat16_rn(v0), hh1 = __float2bfloat16_rn(v1);
        __nv_bfloat16 ll0 = __float2bfloat16_rn(v0 - __bfloat162float(hh0));
        __nv_bfloat16 ll1 = __float2bfloat16_rn(v1 - __bfloat162float(hh1));
        *(__nv_bfloat162*)(g_vth + i0 + p * 2) = __halves2bfloat162(hh0, hh1);
        *(__nv_bfloat162*)(g_vtl + i0 + p * 2) = __halves2bfloat162(ll0, ll1);
    }
}

// ------------------------- launch ------------------------------------------
extern "C" void kernel_launch(void* const* d_in, const int* in_sizes, int n_in,
                              void* d_out, int out_size)
{
    const float* x    = (const float*)d_in[0];
    const int*   task = (const int*)  d_in[1];
    const float* Wb1  = (const float*)d_in[2];
    const float* bb1  = (const float*)d_in[3];
    const float* Wb2  = (const float*)d_in[4];
    const float* bb2  = (const float*)d_in[5];
    const float* We1  = (const float*)d_in[6];
    const float* be1  = (const float*)d_in[7];
    const float* We2  = (const float*)d_in[8];
    const float* be2  = (const float*)d_in[9];
    const float* Wv   = (const float*)d_in[10];
    const float* bv   = (const float*)d_in[11];
    const float* Wk   = (const float*)d_in[12];
    const float* bk   = (const float*)d_in[13];
    const float* Wq   = (const float*)d_in[14];
    const float* bq   = (const float*)d_in[15];
    const float* Wt1  = (const float*)d_in[16];
    const float* bt1  = (const float*)d_in[17];
    const float* Wl   = (const float*)d_in[18];
    const float* bl   = (const float*)d_in[19];
    float* out = (float*)d_out;

#define SYM(p, s) do { void* _t; cudaGetSymbolAddress(&_t, s); p = (decltype(p))_t; } while (0)
    __nv_bfloat16 *xh, *xl, *h1h, *h1l, *hh, *hl, *e1h, *e1l, *e2h, *e2l;
    __nv_bfloat16 *vth, *vtl, *rh, *rl, *th, *tl;
    __nv_bfloat16 *Wb1h, *Wb1l, *Wb2h, *Wb2l, *We1h, *We1l, *We2h, *We2l;
    __nv_bfloat16 *Wvh, *Wvl, *Wt1h, *Wt1l, *Wlh, *Wll;
    float *sc;
    SYM(xh, g_xh);  SYM(xl, g_xl);  SYM(h1h, g_h1h); SYM(h1l, g_h1l);
    SYM(hh, g_hh);  SYM(hl, g_hl);  SYM(e1h, g_e1h); SYM(e1l, g_e1l);
    SYM(e2h, g_e2h); SYM(e2l, g_e2l); SYM(vth, g_vth); SYM(vtl, g_vtl);
    SYM(rh, g_rh);  SYM(rl, g_rl);  SYM(th, g_th);  SYM(tl, g_tl);
    SYM(Wb1h, g_Wb1h); SYM(Wb1l, g_Wb1l); SYM(Wb2h, g_Wb2h); SYM(Wb2l, g_Wb2l);
    SYM(We1h, g_We1h); SYM(We1l, g_We1l); SYM(We2h, g_We2h); SYM(We2l, g_We2l);
    SYM(Wvh, g_Wvh); SYM(Wvl, g_Wvl); SYM(Wt1h, g_Wt1h); SYM(Wt1l, g_Wt1l);
    SYM(Wlh, g_Wlh); SYM(Wll, g_Wll); SYM(sc, g_s);

    const int SMEM = 2 * STAGEB;   // 81920
    cudaFuncSetAttribute(mma_gemm<EPI_RELU >, cudaFuncAttributeMaxDynamicSharedMemorySize, SMEM);
    cudaFuncSetAttribute(mma_gemm<EPI_VSUM >, cudaFuncAttributeMaxDynamicSharedMemorySize, SMEM);
    cudaFuncSetAttribute(mma_gemm<EPI_SPLIT>, cudaFuncAttributeMaxDynamicSharedMemorySize, SMEM);

    dim3 tb(32, 8);
    transpose_split_k<<<dim3(OBSD / 32, DH / 32, 1),   tb>>>(Wb1, Wb1h, Wb1l, OBSD, DH, OBSD, 0);
    transpose_split_k<<<dim3(DH / 32, DH / 32, 1),     tb>>>(Wb2, Wb2h, Wb2l, DH, DH, DH, 0);
    transpose_split_k<<<dim3(DH / 32, DH / 32, NEXP),  tb>>>(We1, We1h, We1l, DH, DH, DH, (size_t)DH * DH);
    transpose_split_k<<<dim3(DH / 32, DH / 32, NEXP),  tb>>>(We2, We2h, We2l, DH, DH, DH, (size_t)DH * DH);
    transpose_split_k<<<dim3(DH / 32, DVV / 32, NEXP), tb>>>(Wv, Wvh, Wvl, DH, DVV, NDH8, (size_t)DH);
    transpose_split_k<<<dim3(DVV / 32, DH / 32, 1),    tb>>>(Wt1, Wt1h, Wt1l, DVV, DH, DVV, 0);
    transpose_split_k<<<dim3(DH / 32, NOUT / 32, 1),   tb>>>(Wl, Wlh, Wll, DH, NOUT, DH, 0);

    split_k<<<(BATCH * OBSD + 255) / 256, 256>>>(x, xh, xl, BATCH * OBSD);
    prep_k<<<1, 256>>>(Wq, bq, bk, task);
    wn_k<<<NEXP * DH / 8, 256>>>(Wk);

    // base MLP
    mma_gemm<EPI_RELU><<<dim3(8, 32), 256, SMEM>>>(
        xh, xl, OBSD, 0, Wb1h, Wb1l, OBSD, 0, bb1, 0, OBSD,
        nullptr, h1h, h1l, DH, 0, nullptr, nullptr);
    mma_gemm<EPI_RELU><<<dim3(8, 32), 256, SMEM>>>(
        h1h, h1l, DH, 0, Wb2h, Wb2l, DH, 0, bb2, 0, DH,
        nullptr, hh, hl, DH, 0, nullptr, nullptr);

    // all experts e1: one GEMM, N = 8192 (B rows stacked), bias = be1 flat
    mma_gemm<EPI_RELU><<<dim3(NDH8 / 128, 32), 256, SMEM>>>(
        hh, hl, DH, 0, We1h, We1l, DH, 0, be1, 0, DH,
        nullptr, e1h, e1l, NDH8, 0, nullptr, nullptr);

    // all experts e2: z-batched block-diagonal GEMM
    mma_gemm<EPI_RELU><<<dim3(DH / 128, 32, NEXP), 256, SMEM>>>(
        e1h, e1l, NDH8, DH, We2h, We2l, DH, DH * DH, be2, DH, DH,
        nullptr, e2h, e2l, NDH8, DH, nullptr, nullptr);

    // attention scale per (expert, row); scaled-activation split
    expkq_k<<<dim3(BATCH / 8, NEXP), 256>>>();
    scale_split_k<<<(int)(((size_t)BATCH * NDH8 / 8) / 256), 256>>>();

    // fused v-sum: single GEMM over K = 8192, bias = sum_n bv[n]*s[n,b] in epilogue
    mma_gemm<EPI_VSUM><<<dim3(DVV / 128, 32), 256, SMEM>>>(
        vth, vtl, NDH8, 0, Wvh, Wvl, NDH8, 0, nullptr, 0, NDH8,
        nullptr, rh, rl, DVV, 0, sc, bv);

    // tower + head
    mma_gemm<EPI_RELU><<<dim3(DH / 128, 32), 256, SMEM>>>(
        rh, rl, DVV, 0, Wt1h, Wt1l, DVV, 0, bt1, 0, DVV,
        nullptr, th, tl, DH, 0, nullptr, nullptr);
    mma_gemm<EPI_SPLIT><<<dim3(1, 32), 256, SMEM>>>(
        th, tl, DH, 0, Wlh, Wll, DH, 0, bl, 0, DH,
        out, nullptr, nullptr, NOUT, 0, nullptr, nullptr);
}

// round 5
// speedup vs baseline: 2.8693x; 1.0240x over previous
#include <cuda_runtime.h>
#include <cuda_bf16.h>
#include <math.h>
#include <stdint.h>

#define BATCH  4096
#define OBSD   512
#define DH     1024
#define NEXP   8
#define DKK    256
#define DVV    1024
#define NTASKS 10
#define NOUT   128
#define NDH8   (NEXP * DH)          // 8192

// ------------------------- scratch (device globals) ------------------------
__device__ __nv_bfloat16 g_xh [BATCH*OBSD], g_xl [BATCH*OBSD];
__device__ __nv_bfloat16 g_h1h[BATCH*DH],   g_h1l[BATCH*DH];
__device__ __nv_bfloat16 g_hh [BATCH*DH],   g_hl [BATCH*DH];
__device__ __nv_bfloat16 g_e1h[(size_t)BATCH*NDH8], g_e1l[(size_t)BATCH*NDH8];
__device__ __nv_bfloat16 g_e2h[(size_t)BATCH*NDH8], g_e2l[(size_t)BATCH*NDH8];
__device__ __nv_bfloat16 g_vth[(size_t)BATCH*NDH8], g_vtl[(size_t)BATCH*NDH8];
__device__ __nv_bfloat16 g_rh [BATCH*DVV],  g_rl [BATCH*DVV];
__device__ __nv_bfloat16 g_th [BATCH*DH],   g_tl [BATCH*DH];

__device__ __nv_bfloat16 g_Wb1h[DH*OBSD],     g_Wb1l[DH*OBSD];
__device__ __nv_bfloat16 g_Wb2h[DH*DH],       g_Wb2l[DH*DH];
__device__ __nv_bfloat16 g_We1h[NEXP*DH*DH],  g_We1l[NEXP*DH*DH];
__device__ __nv_bfloat16 g_We2h[NEXP*DH*DH],  g_We2l[NEXP*DH*DH];
__device__ __nv_bfloat16 g_Wvh [(size_t)DVV*NDH8], g_Wvl [(size_t)DVV*NDH8];
__device__ __nv_bfloat16 g_Wt1h[DH*DVV],      g_Wt1l[DH*DVV];
__device__ __nv_bfloat16 g_Wlh [NOUT*DH],     g_Wll [NOUT*DH];

__device__ float g_q[DKK], g_wn[NEXP*DH], g_cn[NEXP], g_s[NEXP*BATCH];

// ------------------------- PTX helpers -------------------------------------
__device__ __forceinline__ uint32_t smem_u32(const void* p) {
    uint32_t a;
    asm("{ .reg .u64 t; cvta.to.shared.u64 t, %1; cvt.u32.u64 %0, t; }" : "=r"(a) : "l"(p));
    return a;
}
__device__ __forceinline__ void cpa16(uint32_t dst, const void* src) {
    asm volatile("cp.async.cg.shared.global [%0], [%1], 16;" :: "r"(dst), "l"(src));
}
#define CP_COMMIT() asm volatile("cp.async.commit_group;" ::: "memory")
#define CP_WAIT0()  asm volatile("cp.async.wait_group 0;" ::: "memory")
#define CP_WAIT1()  asm volatile("cp.async.wait_group 1;" ::: "memory")

#define LDSM4(r0, r1, r2, r3, addr) \
    asm volatile("ldmatrix.sync.aligned.m8n8.x4.shared.b16 {%0,%1,%2,%3}, [%4];" \
                 : "=r"(r0), "=r"(r1), "=r"(r2), "=r"(r3) : "r"(addr))

#define MMA_BF16(d, a, b0v, b1v) \
    asm volatile("mma.sync.aligned.m16n8k16.row.col.f32.bf16.bf16.f32 " \
                 "{%0,%1,%2,%3},{%4,%5,%6,%7},{%8,%9},{%0,%1,%2,%3};" \
                 : "+f"((d)[0]), "+f"((d)[1]), "+f"((d)[2]), "+f"((d)[3]) \
                 : "r"((a)[0]), "r"((a)[1]), "r"((a)[2]), "r"((a)[3]), \
                   "r"(b0v), "r"(b1v))

// ------------------------- mma.sync bf16x3 GEMM -----------------------------
enum { EPI_RELU = 0, EPI_VSUM = 1, EPI_SPLIT = 2 };

#define LDSR   40                         // smem row stride in elems (pad 8)
#define TILEB  (128 * LDSR * 2)           // bytes per sub-tile
#define STAGEB (4 * TILEB)

template <int EPI>
__global__ __launch_bounds__(256, 2)
void mma_gemm(const __nv_bfloat16* __restrict__ Ah, const __nv_bfloat16* __restrict__ Al,
              int lda, int aoffz,
              const __nv_bfloat16* __restrict__ Bh, const __nv_bfloat16* __restrict__ Bl,
              int ldb, int boffz,
              const float* __restrict__ bias, int biasoffz,
              int K,
              float* __restrict__ Cf,
              __nv_bfloat16* __restrict__ Ch, __nv_bfloat16* __restrict__ Cl,
              int ldc, int coffz,
              const float* __restrict__ sarr, const float* __restrict__ bvv)
{
    extern __shared__ char smem[];
    const uint32_t sbuf = smem_u32(smem);
    const int tid = threadIdx.x, wid = tid >> 5, lane = tid & 31;
    const int z = blockIdx.z;
    const int m0 = blockIdx.y * 128, n0 = blockIdx.x * 128;
    const int warp_m = (wid >> 1) * 32;
    const int warp_n = (wid & 1) * 64;

    const __nv_bfloat16* Abase_h = Ah + (size_t)m0 * lda + (size_t)z * aoffz;
    const __nv_bfloat16* Abase_l = Al + (size_t)m0 * lda + (size_t)z * aoffz;
    const __nv_bfloat16* Bbase_h = Bh + (size_t)z * boffz + (size_t)n0 * ldb;
    const __nv_bfloat16* Bbase_l = Bl + (size_t)z * boffz + (size_t)n0 * ldb;

    float acc[2][8][4];
#pragma unroll
    for (int a = 0; a < 2; a++)
#pragma unroll
        for (int b = 0; b < 8; b++)
#pragma unroll
            for (int c = 0; c < 4; c++) acc[a][b][c] = 0.f;

    const int KT = K >> 5;

    auto load_stage = [&](int kt, int s) {
        const uint32_t base = sbuf + s * STAGEB;
        const int k0 = kt << 5;
#pragma unroll
        for (int part = 0; part < 4; part++) {
            const __nv_bfloat16* src =
                (part == 0 ? Abase_h : part == 1 ? Abase_l : part == 2 ? Bbase_h : Bbase_l);
            const int ld = (part < 2) ? lda : ldb;
            const uint32_t dstb = base + part * TILEB;
#pragma unroll
            for (int i = 0; i < 2; i++) {
                int idx = i * 256 + tid;
                int row = idx >> 2, gc = idx & 3;
                cpa16(dstb + (uint32_t)(row * LDSR + gc * 8) * 2,
                      src + (size_t)row * ld + k0 + gc * 8);
            }
        }
        CP_COMMIT();
    };

    load_stage(0, 0);
    load_stage(1, 1);

    for (int kt = 0; kt < KT; kt++) {
        const int s = kt & 1;
        if (kt == KT - 1) { CP_WAIT0(); } else { CP_WAIT1(); }
        __syncthreads();

        const uint32_t base = sbuf + s * STAGEB;
#pragma unroll
        for (int kk = 0; kk < 2; kk++) {
            const int ko = kk * 16;
            uint32_t ah[2][4], al[2][4];
#pragma unroll
            for (int mt = 0; mt < 2; mt++) {
                const uint32_t arow = warp_m + mt * 16 + ((lane >> 3) & 1) * 8 + (lane & 7);
                const uint32_t acol = ko + (lane >> 4) * 8;
                const uint32_t ad = base + (arow * LDSR + acol) * 2;
                LDSM4(ah[mt][0], ah[mt][1], ah[mt][2], ah[mt][3], ad);
                LDSM4(al[mt][0], al[mt][1], al[mt][2], al[mt][3], ad + TILEB);
            }
#pragma unroll
            for (int np = 0; np < 4; np++) {
                const uint32_t nrow = warp_n + np * 16 + ((lane >> 4) & 1) * 8 + (lane & 7);
                const uint32_t kcol = ko + ((lane >> 3) & 1) * 8;
                const uint32_t bd = base + 2 * TILEB + (nrow * LDSR + kcol) * 2;
                uint32_t bh[4], bl[4];
                LDSM4(bh[0], bh[1], bh[2], bh[3], bd);
                LDSM4(bl[0], bl[1], bl[2], bl[3], bd + TILEB);
                // pass 1: Ah x Bh   (4 independent accs)
                MMA_BF16(acc[0][np * 2],     ah[0], bh[0], bh[1]);
                MMA_BF16(acc[1][np * 2],     ah[1], bh[0], bh[1]);
                MMA_BF16(acc[0][np * 2 + 1], ah[0], bh[2], bh[3]);
                MMA_BF16(acc[1][np * 2 + 1], ah[1], bh[2], bh[3]);
                // pass 2: Ah x Bl
                MMA_BF16(acc[0][np * 2],     ah[0], bl[0], bl[1]);
                MMA_BF16(acc[1][np * 2],     ah[1], bl[0], bl[1]);
                MMA_BF16(acc[0][np * 2 + 1], ah[0], bl[2], bl[3]);
                MMA_BF16(acc[1][np * 2 + 1], ah[1], bl[2], bl[3]);
                // pass 3: Al x Bh
                MMA_BF16(acc[0][np * 2],     al[0], bh[0], bh[1]);
                MMA_BF16(acc[1][np * 2],     al[1], bh[0], bh[1]);
                MMA_BF16(acc[0][np * 2 + 1], al[0], bh[2], bh[3]);
                MMA_BF16(acc[1][np * 2 + 1], al[1], bh[2], bh[3]);
            }
        }
        __syncthreads();
        if (kt + 2 < KT) load_stage(kt + 2, s);
    }

    // ------------- epilogue -------------
    const int tr = lane >> 2, tc = (lane & 3) * 2;
#pragma unroll
    for (int mt = 0; mt < 2; mt++) {
#pragma unroll
        for (int half = 0; half < 2; half++) {
            const int r = m0 + warp_m + mt * 16 + tr + half * 8;
            float sv8[NEXP];
            if (EPI == EPI_VSUM) {
#pragma unroll
                for (int n = 0; n < NEXP; n++) sv8[n] = sarr[n * BATCH + r];
            }
#pragma unroll
            for (int j = 0; j < 8; j++) {
                const int col = n0 + warp_n + j * 8 + tc;
                float v0 = acc[mt][j][half * 2];
                float v1 = acc[mt][j][half * 2 + 1];

                if (EPI == EPI_RELU) {
                    v0 += bias[(size_t)z * biasoffz + col];
                    v1 += bias[(size_t)z * biasoffz + col + 1];
                    v0 = fmaxf(v0, 0.f); v1 = fmaxf(v1, 0.f);
                    __nv_bfloat16 h0 = __float2bfloat16_rn(v0);
                    __nv_bfloat16 h1 = __float2bfloat16_rn(v1);
                    __nv_bfloat16 l0 = __float2bfloat16_rn(v0 - __bfloat162float(h0));
                    __nv_bfloat16 l1 = __float2bfloat16_rn(v1 - __bfloat162float(h1));
                    size_t o = (size_t)r * ldc + (size_t)z * coffz + col;
                    *(__nv_bfloat162*)(Ch + o) = __halves2bfloat162(h0, h1);
                    *(__nv_bfloat162*)(Cl + o) = __halves2bfloat162(l0, l1);
                } else if (EPI == EPI_VSUM) {
#pragma unroll
                    for (int n = 0; n < NEXP; n++) {
                        v0 += bvv[n * DVV + col]     * sv8[n];
                        v1 += bvv[n * DVV + col + 1] * sv8[n];
                    }
                    __nv_bfloat16 h0 = __float2bfloat16_rn(v0);
                    __nv_bfloat16 h1 = __float2bfloat16_rn(v1);
                    __nv_bfloat16 l0 = __float2bfloat16_rn(v0 - __bfloat162float(h0));
                    __nv_bfloat16 l1 = __float2bfloat16_rn(v1 - __bfloat162float(h1));
                    size_t o = (size_t)r * ldc + col;
                    *(__nv_bfloat162*)(Ch + o) = __halves2bfloat162(h0, h1);
                    *(__nv_bfloat162*)(Cl + o) = __halves2bfloat162(l0, l1);
                } else {   // EPI_SPLIT
                    v0 += bias[col]; v1 += bias[col + 1];
                    if (col < 64) {
                        Cf[(size_t)r * 64 + col]     = v0;
                        Cf[(size_t)r * 64 + col + 1] = v1;
                    } else {
                        float l0 = fminf(fmaxf(v0, -20.f), 2.f);
                        float l1 = fminf(fmaxf(v1, -20.f), 2.f);
                        Cf[(size_t)BATCH * 64 + (size_t)r * 64 + (col - 64)]     = expf(l0);
                        Cf[(size_t)BATCH * 64 + (size_t)r * 64 + (col - 63)]     = expf(l1);
                        Cf[(size_t)2 * BATCH * 64 + (size_t)r * 64 + (col - 64)] = l0;
                        Cf[(size_t)2 * BATCH * 64 + (size_t)r * 64 + (col - 63)] = l1;
                    }
                }
            }
        }
    }
}

// ------------------------- prep kernels ------------------------------------
__global__ void transpose_split_k(const float* __restrict__ W,
                                  __nv_bfloat16* __restrict__ Th,
                                  __nv_bfloat16* __restrict__ Tl,
                                  int K, int N, int ors, size_t zoff)
{
    __shared__ float tile[32][33];
    const int z = blockIdx.z;
    const float* Wb = W + (size_t)z * K * N;
    const int k0 = blockIdx.x * 32, n0 = blockIdx.y * 32;
    const int tx = threadIdx.x, ty = threadIdx.y;
#pragma unroll
    for (int i = ty; i < 32; i += 8)
        tile[i][tx] = Wb[(size_t)(k0 + i) * N + n0 + tx];
    __syncthreads();
#pragma unroll
    for (int i = ty; i < 32; i += 8) {
        float v = tile[tx][i];
        __nv_bfloat16 h = __float2bfloat16_rn(v);
        __nv_bfloat16 l = __float2bfloat16_rn(v - __bfloat162float(h));
        size_t o = (size_t)z * zoff + (size_t)(n0 + i) * ors + k0 + tx;
        Th[o] = h; Tl[o] = l;
    }
}

__global__ void split_k(const float* __restrict__ X, __nv_bfloat16* __restrict__ Xh,
                        __nv_bfloat16* __restrict__ Xl, int n)
{
    int i = blockIdx.x * 256 + threadIdx.x;
    if (i < n) {
        float v = X[i];
        __nv_bfloat16 h = __float2bfloat16_rn(v);
        Xh[i] = h;
        Xl[i] = __float2bfloat16_rn(v - __bfloat162float(h));
    }
}

// q = Wq[t][t,:] + bq[t];  cn[n] = dot(bk[n], q)
__global__ void prep_k(const float* __restrict__ Wq, const float* __restrict__ bq,
                       const float* __restrict__ bk, const int* __restrict__ task_id)
{
    __shared__ float qs[DKK];
    const int t = *task_id;
    const int tid = threadIdx.x;
    float qv = Wq[(size_t)(t * NTASKS + t) * DKK + tid] + bq[(size_t)t * DKK + tid];
    g_q[tid] = qv;
    qs[tid]  = qv;
    __syncthreads();
    const int w = tid >> 5, lane = tid & 31;
    float sum = 0.f;
#pragma unroll
    for (int k = lane; k < DKK; k += 32) sum += bk[(size_t)w * DKK + k] * qs[k];
#pragma unroll
    for (int o = 16; o; o >>= 1) sum += __shfl_xor_sync(0xffffffffu, sum, o);
    if (lane == 0) g_cn[w] = sum;
}

// wn[i] = dot(Wk[i,:], q)
__global__ void wn_k(const float* __restrict__ Wk)
{
    const int tid = threadIdx.x, w = tid >> 5, lane = tid & 31;
    const int row = blockIdx.x * 8 + w;
    const float* wr = Wk + (size_t)row * DKK;
    float sum = 0.f;
#pragma unroll
    for (int k = lane; k < DKK; k += 32) sum += wr[k] * g_q[k];
#pragma unroll
    for (int o = 16; o; o >>= 1) sum += __shfl_xor_sync(0xffffffffu, sum, o);
    if (lane == 0) g_wn[row] = sum;
}

// fused: s[n][b] = dot(e2[b, n*DH..], wn[n]) + cn[n], then
// vt[b, n*DH+d] = split(e2[b,n*DH+d] * s[n][b]).  Warp-private smem cache.
__global__ void expkq_scale_k()
{
    __shared__ uint32_t shh[8][512], shl[8][512];   // 32 KB: bf16x2 pairs
    const int tid = threadIdx.x, w = tid >> 5, lane = tid & 31;
    const int row = blockIdx.x * 8 + w;
    const int n = blockIdx.y;
    const size_t base = (size_t)row * NDH8 + (size_t)n * DH;
    const float* wn = g_wn + n * DH;
    float sum = 0.f;
#pragma unroll 4
    for (int it = 0; it < 16; it++) {
        const int k2 = it * 32 + lane;            // pair index
        uint32_t h2 = *(const uint32_t*)(g_e2h + base + k2 * 2);
        uint32_t l2 = *(const uint32_t*)(g_e2l + base + k2 * 2);
        shh[w][k2] = h2; shl[w][k2] = l2;
        __nv_bfloat162 hb = *(__nv_bfloat162*)&h2;
        __nv_bfloat162 lb = *(__nv_bfloat162*)&l2;
        float2 wv = *(const float2*)(wn + k2 * 2);
        sum += (__bfloat162float(hb.x) + __bfloat162float(lb.x)) * wv.x
             + (__bfloat162float(hb.y) + __bfloat162float(lb.y)) * wv.y;
    }
#pragma unroll
    for (int o = 16; o; o >>= 1) sum += __shfl_xor_sync(0xffffffffu, sum, o);
    const float s = sum + g_cn[n];
    if (lane == 0) g_s[n * BATCH + row] = s;
#pragma unroll 4
    for (int it = 0; it < 16; it++) {
        const int k2 = it * 32 + lane;
        uint32_t h2 = shh[w][k2], l2 = shl[w][k2];
        __nv_bfloat162 hb = *(__nv_bfloat162*)&h2;
        __nv_bfloat162 lb = *(__nv_bfloat162*)&l2;
        float v0 = (__bfloat162float(hb.x) + __bfloat162float(lb.x)) * s;
        float v1 = (__bfloat162float(hb.y) + __bfloat162float(lb.y)) * s;
        __nv_bfloat16 hh0 = __float2bfloat16_rn(v0), hh1 = __float2bfloat16_rn(v1);
        __nv_bfloat16 ll0 = __float2bfloat16_rn(v0 - __bfloat162float(hh0));
        __nv_bfloat16 ll1 = __float2bfloat16_rn(v1 - __bfloat162float(hh1));
        *(__nv_bfloat162*)(g_vth + base + k2 * 2) = __halves2bfloat162(hh0, hh1);
        *(__nv_bfloat162*)(g_vtl + base + k2 * 2) = __halves2bfloat162(ll0, ll1);
    }
}

// ------------------------- launch ------------------------------------------
extern "C" void kernel_launch(void* const* d_in, const int* in_sizes, int n_in,
                              void* d_out, int out_size)
{
    const float* x    = (const float*)d_in[0];
    const int*   task = (const int*)  d_in[1];
    const float* Wb1  = (const float*)d_in[2];
    const float* bb1  = (const float*)d_in[3];
    const float* Wb2  = (const float*)d_in[4];
    const float* bb2  = (const float*)d_in[5];
    const float* We1  = (const float*)d_in[6];
    const float* be1  = (const float*)d_in[7];
    const float* We2  = (const float*)d_in[8];
    const float* be2  = (const float*)d_in[9];
    const float* Wv   = (const float*)d_in[10];
    const float* bv   = (const float*)d_in[11];
    const float* Wk   = (const float*)d_in[12];
    const float* bk   = (const float*)d_in[13];
    const float* Wq   = (const float*)d_in[14];
    const float* bq   = (const float*)d_in[15];
    const float* Wt1  = (const float*)d_in[16];
    const float* bt1  = (const float*)d_in[17];
    const float* Wl   = (const float*)d_in[18];
    const float* bl   = (const float*)d_in[19];
    float* out = (float*)d_out;

#define SYM(p, s) do { void* _t; cudaGetSymbolAddress(&_t, s); p = (decltype(p))_t; } while (0)
    __nv_bfloat16 *xh, *xl, *h1h, *h1l, *hh, *hl, *e1h, *e1l, *e2h, *e2l;
    __nv_bfloat16 *vth, *vtl, *rh, *rl, *th, *tl;
    __nv_bfloat16 *Wb1h, *Wb1l, *Wb2h, *Wb2l, *We1h, *We1l, *We2h, *We2l;
    __nv_bfloat16 *Wvh, *Wvl, *Wt1h, *Wt1l, *Wlh, *Wll;
    float *sc;
    SYM(xh, g_xh);  SYM(xl, g_xl);  SYM(h1h, g_h1h); SYM(h1l, g_h1l);
    SYM(hh, g_hh);  SYM(hl, g_hl);  SYM(e1h, g_e1h); SYM(e1l, g_e1l);
    SYM(e2h, g_e2h); SYM(e2l, g_e2l); SYM(vth, g_vth); SYM(vtl, g_vtl);
    SYM(rh, g_rh);  SYM(rl, g_rl);  SYM(th, g_th);  SYM(tl, g_tl);
    SYM(Wb1h, g_Wb1h); SYM(Wb1l, g_Wb1l); SYM(Wb2h, g_Wb2h); SYM(Wb2l, g_Wb2l);
    SYM(We1h, g_We1h); SYM(We1l, g_We1l); SYM(We2h, g_We2h); SYM(We2l, g_We2l);
    SYM(Wvh, g_Wvh); SYM(Wvl, g_Wvl); SYM(Wt1h, g_Wt1h); SYM(Wt1l, g_Wt1l);
    SYM(Wlh, g_Wlh); SYM(Wll, g_Wll); SYM(sc, g_s);

    const int SMEM = 2 * STAGEB;   // 81920
    cudaFuncSetAttribute(mma_gemm<EPI_RELU >, cudaFuncAttributeMaxDynamicSharedMemorySize, SMEM);
    cudaFuncSetAttribute(mma_gemm<EPI_VSUM >, cudaFuncAttributeMaxDynamicSharedMemorySize, SMEM);
    cudaFuncSetAttribute(mma_gemm<EPI_SPLIT>, cudaFuncAttributeMaxDynamicSharedMemorySize, SMEM);

    dim3 tb(32, 8);

    // launch order arranged so ncu (-s 5 -c 1) profiles the full-size GEMM (idx 5)
    split_k<<<(BATCH * OBSD + 255) / 256, 256>>>(x, xh, xl, BATCH * OBSD);          // 0
    transpose_split_k<<<dim3(OBSD / 32, DH / 32, 1),  tb>>>(Wb1, Wb1h, Wb1l, OBSD, DH, OBSD, 0);   // 1
    transpose_split_k<<<dim3(DH / 32, DH / 32, 1),    tb>>>(Wb2, Wb2h, Wb2l, DH, DH, DH, 0);       // 2
    transpose_split_k<<<dim3(DH / 32, DH / 32, NEXP), tb>>>(We1, We1h, We1l, DH, DH, DH, (size_t)DH * DH); // 3

    mma_gemm<EPI_RELU><<<dim3(8, 32), 256, SMEM>>>(                                  // 4: base1
        xh, xl, OBSD, 0, Wb1h, Wb1l, OBSD, 0, bb1, 0, OBSD,
        nullptr, h1h, h1l, DH, 0, nullptr, nullptr);
    mma_gemm<EPI_RELU><<<dim3(8, 32), 256, SMEM>>>(                                  // 5: base2 (profiled)
        h1h, h1l, DH, 0, Wb2h, Wb2l, DH, 0, bb2, 0, DH,
        nullptr, hh, hl, DH, 0, nullptr, nullptr);

    // all experts e1: one GEMM, N = 8192
    mma_gemm<EPI_RELU><<<dim3(NDH8 / 128, 32), 256, SMEM>>>(                         // 6
        hh, hl, DH, 0, We1h, We1l, DH, 0, be1, 0, DH,
        nullptr, e1h, e1l, NDH8, 0, nullptr, nullptr);

    transpose_split_k<<<dim3(DH / 32, DH / 32, NEXP), tb>>>(We2, We2h, We2l, DH, DH, DH, (size_t)DH * DH); // 7

    // all experts e2: z-batched block-diagonal GEMM
    mma_gemm<EPI_RELU><<<dim3(DH / 128, 32, NEXP), 256, SMEM>>>(                     // 8
        e1h, e1l, NDH8, DH, We2h, We2l, DH, DH * DH, be2, DH, DH,
        nullptr, e2h, e2l, NDH8, DH, nullptr, nullptr);

    prep_k<<<1, 256>>>(Wq, bq, bk, task);                                            // 9
    wn_k<<<NEXP * DH / 8, 256>>>(Wk);                                                // 10
    expkq_scale_k<<<dim3(BATCH / 8, NEXP), 256>>>();                                 // 11

    transpose_split_k<<<dim3(DH / 32, DVV / 32, NEXP), tb>>>(Wv, Wvh, Wvl, DH, DVV, NDH8, (size_t)DH); // 12

    // fused v-sum: single GEMM over K = 8192, bias = sum_n bv[n]*s[n,b] in epilogue
    mma_gemm<EPI_VSUM><<<dim3(DVV / 128, 32), 256, SMEM>>>(                          // 13
        vth, vtl, NDH8, 0, Wvh, Wvl, NDH8, 0, nullptr, 0, NDH8,
        nullptr, rh, rl, DVV, 0, sc, bv);

    transpose_split_k<<<dim3(DVV / 32, DH / 32, 1), tb>>>(Wt1, Wt1h, Wt1l, DVV, DH, DVV, 0);  // 14
    mma_gemm<EPI_RELU><<<dim3(DH / 128, 32), 256, SMEM>>>(                           // 15
        rh, rl, DVV, 0, Wt1h, Wt1l, DVV, 0, bt1, 0, DVV,
        nullptr, th, tl, DH, 0, nullptr, nullptr);

    transpose_split_k<<<dim3(DH / 32, NOUT / 32, 1), tb>>>(Wl, Wlh, Wll, DH, NOUT, DH, 0);    // 16
    mma_gemm<EPI_SPLIT><<<dim3(1, 32), 256, SMEM>>>(                                 // 17
        th, tl, DH, 0, Wlh, Wll, DH, 0, bl, 0, DH,
        out, nullptr, nullptr, NOUT, 0, nullptr, nullptr);
}

// round 6
// speedup vs baseline: 3.4991x; 1.2195x over previous
#include <cuda_runtime.h>
#include <cuda_bf16.h>
#include <math.h>
#include <stdint.h>

#define BATCH  4096
#define OBSD   512
#define DH     1024
#define NEXP   8
#define DKK    256
#define DVV    1024
#define NTASKS 10
#define NOUT   128
#define NDH8   (NEXP * DH)          // 8192

// ------------------------- scratch (device globals) ------------------------
__device__ __nv_bfloat16 g_xh [BATCH*OBSD], g_xl [BATCH*OBSD];
__device__ __nv_bfloat16 g_h1h[BATCH*DH],   g_h1l[BATCH*DH];
__device__ __nv_bfloat16 g_hh [BATCH*DH],   g_hl [BATCH*DH];
__device__ __nv_bfloat16 g_e1h[(size_t)BATCH*NDH8], g_e1l[(size_t)BATCH*NDH8];
__device__ __nv_bfloat16 g_e2h[(size_t)BATCH*NDH8], g_e2l[(size_t)BATCH*NDH8];
__device__ __nv_bfloat16 g_vth[(size_t)BATCH*NDH8], g_vtl[(size_t)BATCH*NDH8];
__device__ __nv_bfloat16 g_rh [BATCH*DVV],  g_rl [BATCH*DVV];
__device__ __nv_bfloat16 g_th [BATCH*DH],   g_tl [BATCH*DH];

__device__ __nv_bfloat16 g_Wb1h[DH*OBSD],     g_Wb1l[DH*OBSD];
__device__ __nv_bfloat16 g_Wb2h[DH*DH],       g_Wb2l[DH*DH];
__device__ __nv_bfloat16 g_We1h[NEXP*DH*DH],  g_We1l[NEXP*DH*DH];
__device__ __nv_bfloat16 g_We2h[NEXP*DH*DH],  g_We2l[NEXP*DH*DH];
__device__ __nv_bfloat16 g_Wvh [(size_t)DVV*NDH8], g_Wvl [(size_t)DVV*NDH8];
__device__ __nv_bfloat16 g_Wt1h[DH*DVV],      g_Wt1l[DH*DVV];
__device__ __nv_bfloat16 g_Wlh [NOUT*DH],     g_Wll [NOUT*DH];

__device__ float g_q[DKK], g_wn[NEXP*DH], g_cn[NEXP], g_s[NEXP*BATCH];

// ------------------------- PTX helpers -------------------------------------
__device__ __forceinline__ uint32_t smem_u32(const void* p) {
    uint32_t a;
    asm("{ .reg .u64 t; cvta.to.shared.u64 t, %1; cvt.u32.u64 %0, t; }" : "=r"(a) : "l"(p));
    return a;
}
__device__ __forceinline__ void cpa16(uint32_t dst, const void* src) {
    asm volatile("cp.async.cg.shared.global [%0], [%1], 16;" :: "r"(dst), "l"(src));
}
#define CP_COMMIT() asm volatile("cp.async.commit_group;" ::: "memory")
#define CP_WAIT0()  asm volatile("cp.async.wait_group 0;" ::: "memory")
#define CP_WAIT1()  asm volatile("cp.async.wait_group 1;" ::: "memory")

#define LDSM4(r0, r1, r2, r3, addr) \
    asm volatile("ldmatrix.sync.aligned.m8n8.x4.shared.b16 {%0,%1,%2,%3}, [%4];" \
                 : "=r"(r0), "=r"(r1), "=r"(r2), "=r"(r3) : "r"(addr))

#define MMA_BF16(d, a, b0v, b1v) \
    asm volatile("mma.sync.aligned.m16n8k16.row.col.f32.bf16.bf16.f32 " \
                 "{%0,%1,%2,%3},{%4,%5,%6,%7},{%8,%9},{%0,%1,%2,%3};" \
                 : "+f"((d)[0]), "+f"((d)[1]), "+f"((d)[2]), "+f"((d)[3]) \
                 : "r"((a)[0]), "r"((a)[1]), "r"((a)[2]), "r"((a)[3]), \
                   "r"(b0v), "r"(b1v))

// ------------------------- mma.sync bf16x3 GEMM -----------------------------
// Pad-free XOR swizzle: 128 rows x 32 bf16 cols = 64B/row; 16B unit index
// swizzled as  unit' = unit ^ ((row>>1)&3).  Conflict-free for cp.async
// stores and all ldmatrix phases (8 distinct 16B slots mod 128B).
enum { EPI_RELU = 0, EPI_VSUM = 1, EPI_SPLIT = 2 };

#define TILEB  8192                       // 128 * 64B
#define STAGEB (4 * TILEB)                // Ah,Al,Bh,Bl = 32 KB
#define NSTAGE 3
#define SMEMSZ (NSTAGE * STAGEB)          // 98304

template <int EPI>
__global__ __launch_bounds__(256, 2)
void mma_gemm(const __nv_bfloat16* __restrict__ Ah, const __nv_bfloat16* __restrict__ Al,
              int lda, int aoffz,
              const __nv_bfloat16* __restrict__ Bh, const __nv_bfloat16* __restrict__ Bl,
              int ldb, int boffz,
              const float* __restrict__ bias, int biasoffz,
              int K,
              float* __restrict__ Cf,
              __nv_bfloat16* __restrict__ Ch, __nv_bfloat16* __restrict__ Cl,
              int ldc, int coffz,
              const float* __restrict__ sarr, const float* __restrict__ bvv)
{
    extern __shared__ char smem[];
    const uint32_t sbuf = smem_u32(smem);
    const int tid = threadIdx.x, wid = tid >> 5, lane = tid & 31;
    const int z = blockIdx.z;
    const int m0 = blockIdx.y * 128, n0 = blockIdx.x * 128;
    const int warp_m = (wid >> 1) * 32;
    const int warp_n = (wid & 1) * 64;

    const __nv_bfloat16* Abase_h = Ah + (size_t)m0 * lda + (size_t)z * aoffz;
    const __nv_bfloat16* Abase_l = Al + (size_t)m0 * lda + (size_t)z * aoffz;
    const __nv_bfloat16* Bbase_h = Bh + (size_t)z * boffz + (size_t)n0 * ldb;
    const __nv_bfloat16* Bbase_l = Bl + (size_t)z * boffz + (size_t)n0 * ldb;

    float acc[2][8][4];
#pragma unroll
    for (int a = 0; a < 2; a++)
#pragma unroll
        for (int b = 0; b < 8; b++)
#pragma unroll
            for (int c = 0; c < 4; c++) acc[a][b][c] = 0.f;

    const int KT = K >> 5;

    auto load_stage = [&](int kt, int s) {
        const uint32_t base = sbuf + s * STAGEB;
        const int k0 = kt << 5;
#pragma unroll
        for (int part = 0; part < 4; part++) {
            const __nv_bfloat16* src =
                (part == 0 ? Abase_h : part == 1 ? Abase_l : part == 2 ? Bbase_h : Bbase_l);
            const int ld = (part < 2) ? lda : ldb;
            const uint32_t dstb = base + part * TILEB;
#pragma unroll
            for (int i = 0; i < 2; i++) {
                int idx = i * 256 + tid;           // 512 granules of 16B
                int row = idx >> 2, g = idx & 3;
                int unit = g ^ ((row >> 1) & 3);
                cpa16(dstb + (uint32_t)(row * 64 + unit * 16),
                      src + (size_t)row * ld + k0 + g * 8);
            }
        }
        CP_COMMIT();
    };

    load_stage(0, 0);
    load_stage(1, 1);

    int s = 0, ls = 2;
    for (int kt = 0; kt < KT; kt++) {
        if (kt == KT - 1) { CP_WAIT0(); } else { CP_WAIT1(); }
        __syncthreads();

        const uint32_t base = sbuf + s * STAGEB;
#pragma unroll
        for (int kk = 0; kk < 2; kk++) {
            uint32_t ah[2][4], al[2][4];
#pragma unroll
            for (int mt = 0; mt < 2; mt++) {
                const uint32_t arow = warp_m + mt * 16 + ((lane >> 3) & 1) * 8 + (lane & 7);
                const uint32_t cu = (kk * 2 + (lane >> 4)) ^ ((arow >> 1) & 3);
                const uint32_t ad = base + arow * 64 + cu * 16;
                LDSM4(ah[mt][0], ah[mt][1], ah[mt][2], ah[mt][3], ad);
                LDSM4(al[mt][0], al[mt][1], al[mt][2], al[mt][3], ad + TILEB);
            }
#pragma unroll
            for (int np = 0; np < 4; np++) {
                const uint32_t nrow = warp_n + np * 16 + ((lane >> 4) & 1) * 8 + (lane & 7);
                const uint32_t cu = (kk * 2 + ((lane >> 3) & 1)) ^ ((nrow >> 1) & 3);
                const uint32_t bd = base + 2 * TILEB + nrow * 64 + cu * 16;
                uint32_t bh[4], bl[4];
                LDSM4(bh[0], bh[1], bh[2], bh[3], bd);
                LDSM4(bl[0], bl[1], bl[2], bl[3], bd + TILEB);
                // pass 1: Ah x Bh   (4 independent accs)
                MMA_BF16(acc[0][np * 2],     ah[0], bh[0], bh[1]);
                MMA_BF16(acc[1][np * 2],     ah[1], bh[0], bh[1]);
                MMA_BF16(acc[0][np * 2 + 1], ah[0], bh[2], bh[3]);
                MMA_BF16(acc[1][np * 2 + 1], ah[1], bh[2], bh[3]);
                // pass 2: Ah x Bl
                MMA_BF16(acc[0][np * 2],     ah[0], bl[0], bl[1]);
                MMA_BF16(acc[1][np * 2],     ah[1], bl[0], bl[1]);
                MMA_BF16(acc[0][np * 2 + 1], ah[0], bl[2], bl[3]);
                MMA_BF16(acc[1][np * 2 + 1], ah[1], bl[2], bl[3]);
                // pass 3: Al x Bh
                MMA_BF16(acc[0][np * 2],     al[0], bh[0], bh[1]);
                MMA_BF16(acc[1][np * 2],     al[1], bh[0], bh[1]);
                MMA_BF16(acc[0][np * 2 + 1], al[0], bh[2], bh[3]);
                MMA_BF16(acc[1][np * 2 + 1], al[1], bh[2], bh[3]);
            }
        }
        // single barrier per chunk: stage (kt+2)%3 was last read at kt-1,
        // ordered by the barrier at the top of this iteration.
        if (kt + 2 < KT) load_stage(kt + 2, ls);
        s  = (s  == NSTAGE - 1) ? 0 : s + 1;
        ls = (ls == NSTAGE - 1) ? 0 : ls + 1;
    }

    // ------------- epilogue -------------
    const int tr = lane >> 2, tc = (lane & 3) * 2;
#pragma unroll
    for (int mt = 0; mt < 2; mt++) {
#pragma unroll
        for (int half = 0; half < 2; half++) {
            const int r = m0 + warp_m + mt * 16 + tr + half * 8;
            float sv8[NEXP];
            if (EPI == EPI_VSUM) {
#pragma unroll
                for (int n = 0; n < NEXP; n++) sv8[n] = sarr[n * BATCH + r];
            }
#pragma unroll
            for (int j = 0; j < 8; j++) {
                const int col = n0 + warp_n + j * 8 + tc;
                float v0 = acc[mt][j][half * 2];
                float v1 = acc[mt][j][half * 2 + 1];

                if (EPI == EPI_RELU) {
                    v0 += bias[(size_t)z * biasoffz + col];
                    v1 += bias[(size_t)z * biasoffz + col + 1];
                    v0 = fmaxf(v0, 0.f); v1 = fmaxf(v1, 0.f);
                    __nv_bfloat16 h0 = __float2bfloat16_rn(v0);
                    __nv_bfloat16 h1 = __float2bfloat16_rn(v1);
                    __nv_bfloat16 l0 = __float2bfloat16_rn(v0 - __bfloat162float(h0));
                    __nv_bfloat16 l1 = __float2bfloat16_rn(v1 - __bfloat162float(h1));
                    size_t o = (size_t)r * ldc + (size_t)z * coffz + col;
                    *(__nv_bfloat162*)(Ch + o) = __halves2bfloat162(h0, h1);
                    *(__nv_bfloat162*)(Cl + o) = __halves2bfloat162(l0, l1);
                } else if (EPI == EPI_VSUM) {
#pragma unroll
                    for (int n = 0; n < NEXP; n++) {
                        v0 += bvv[n * DVV + col]     * sv8[n];
                        v1 += bvv[n * DVV + col + 1] * sv8[n];
                    }
                    __nv_bfloat16 h0 = __float2bfloat16_rn(v0);
                    __nv_bfloat16 h1 = __float2bfloat16_rn(v1);
                    __nv_bfloat16 l0 = __float2bfloat16_rn(v0 - __bfloat162float(h0));
                    __nv_bfloat16 l1 = __float2bfloat16_rn(v1 - __bfloat162float(h1));
                    size_t o = (size_t)r * ldc + col;
                    *(__nv_bfloat162*)(Ch + o) = __halves2bfloat162(h0, h1);
                    *(__nv_bfloat162*)(Cl + o) = __halves2bfloat162(l0, l1);
                } else {   // EPI_SPLIT
                    v0 += bias[col]; v1 += bias[col + 1];
                    if (col < 64) {
                        Cf[(size_t)r * 64 + col]     = v0;
                        Cf[(size_t)r * 64 + col + 1] = v1;
                    } else {
                        float l0 = fminf(fmaxf(v0, -20.f), 2.f);
                        float l1 = fminf(fmaxf(v1, -20.f), 2.f);
                        Cf[(size_t)BATCH * 64 + (size_t)r * 64 + (col - 64)]     = expf(l0);
                        Cf[(size_t)BATCH * 64 + (size_t)r * 64 + (col - 63)]     = expf(l1);
                        Cf[(size_t)2 * BATCH * 64 + (size_t)r * 64 + (col - 64)] = l0;
                        Cf[(size_t)2 * BATCH * 64 + (size_t)r * 64 + (col - 63)] = l1;
                    }
                }
            }
        }
    }
}

// ------------------------- prep kernels ------------------------------------
// (16,16) block; packed bf16x2 stores on the transposed axis.
__global__ void transpose_split_k(const float* __restrict__ W,
                                  __nv_bfloat16* __restrict__ Th,
                                  __nv_bfloat16* __restrict__ Tl,
                                  int K, int N, int ors, size_t zoff)
{
    __shared__ float tile[32][33];
    const int z = blockIdx.z;
    const float* Wb = W + (size_t)z * K * N;
    const int k0 = blockIdx.x * 32, n0 = blockIdx.y * 32;
    const int tx = threadIdx.x, ty = threadIdx.y;   // 16 x 16
#pragma unroll
    for (int ii = 0; ii < 2; ii++)
#pragma unroll
        for (int jj = 0; jj < 2; jj++)
            tile[ty + 16 * ii][tx + 16 * jj] =
                Wb[(size_t)(k0 + ty + 16 * ii) * N + n0 + tx + 16 * jj];
    __syncthreads();
#pragma unroll
    for (int ii = 0; ii < 2; ii++) {
        const int i = ty + 16 * ii;
        float v0 = tile[tx * 2][i], v1 = tile[tx * 2 + 1][i];
        __nv_bfloat16 h0 = __float2bfloat16_rn(v0);
        __nv_bfloat16 h1 = __float2bfloat16_rn(v1);
        __nv_bfloat16 l0 = __float2bfloat16_rn(v0 - __bfloat162float(h0));
        __nv_bfloat16 l1 = __float2bfloat16_rn(v1 - __bfloat162float(h1));
        size_t o = (size_t)z * zoff + (size_t)(n0 + i) * ors + k0 + tx * 2;
        *(__nv_bfloat162*)(Th + o) = __halves2bfloat162(h0, h1);
        *(__nv_bfloat162*)(Tl + o) = __halves2bfloat162(l0, l1);
    }
}

__global__ void split_k(const float* __restrict__ X, __nv_bfloat16* __restrict__ Xh,
                        __nv_bfloat16* __restrict__ Xl, int n)
{
    int i = blockIdx.x * 256 + threadIdx.x;
    if (i < n) {
        float v = X[i];
        __nv_bfloat16 h = __float2bfloat16_rn(v);
        Xh[i] = h;
        Xl[i] = __float2bfloat16_rn(v - __bfloat162float(h));
    }
}

// q = Wq[t][t,:] + bq[t];  cn[n] = dot(bk[n], q)
__global__ void prep_k(const float* __restrict__ Wq, const float* __restrict__ bq,
                       const float* __restrict__ bk, const int* __restrict__ task_id)
{
    __shared__ float qs[DKK];
    const int t = *task_id;
    const int tid = threadIdx.x;
    float qv = Wq[(size_t)(t * NTASKS + t) * DKK + tid] + bq[(size_t)t * DKK + tid];
    g_q[tid] = qv;
    qs[tid]  = qv;
    __syncthreads();
    const int w = tid >> 5, lane = tid & 31;
    float sum = 0.f;
#pragma unroll
    for (int k = lane; k < DKK; k += 32) sum += bk[(size_t)w * DKK + k] * qs[k];
#pragma unroll
    for (int o = 16; o; o >>= 1) sum += __shfl_xor_sync(0xffffffffu, sum, o);
    if (lane == 0) g_cn[w] = sum;
}

// wn[i] = dot(Wk[i,:], q)
__global__ void wn_k(const float* __restrict__ Wk)
{
    const int tid = threadIdx.x, w = tid >> 5, lane = tid & 31;
    const int row = blockIdx.x * 8 + w;
    const float* wr = Wk + (size_t)row * DKK;
    float sum = 0.f;
#pragma unroll
    for (int k = lane; k < DKK; k += 32) sum += wr[k] * g_q[k];
#pragma unroll
    for (int o = 16; o; o >>= 1) sum += __shfl_xor_sync(0xffffffffu, sum, o);
    if (lane == 0) g_wn[row] = sum;
}

// fused: s[n][b] = dot(e2[b, n*DH..], wn[n]) + cn[n], then
// vt[b, n*DH+d] = split(e2[b,n*DH+d] * s[n][b]).
__global__ void expkq_scale_k()
{
    __shared__ uint32_t shh[8][512], shl[8][512];
    const int tid = threadIdx.x, w = tid >> 5, lane = tid & 31;
    const int row = blockIdx.x * 8 + w;
    const int n = blockIdx.y;
    const size_t base = (size_t)row * NDH8 + (size_t)n * DH;
    const float* wn = g_wn + n * DH;
    float sum = 0.f;
#pragma unroll 4
    for (int it = 0; it < 16; it++) {
        const int k2 = it * 32 + lane;
        uint32_t h2 = *(const uint32_t*)(g_e2h + base + k2 * 2);
        uint32_t l2 = *(const uint32_t*)(g_e2l + base + k2 * 2);
        shh[w][k2] = h2; shl[w][k2] = l2;
        __nv_bfloat162 hb = *(__nv_bfloat162*)&h2;
        __nv_bfloat162 lb = *(__nv_bfloat162*)&l2;
        float2 wv = *(const float2*)(wn + k2 * 2);
        sum += (__bfloat162float(hb.x) + __bfloat162float(lb.x)) * wv.x
             + (__bfloat162float(hb.y) + __bfloat162float(lb.y)) * wv.y;
    }
#pragma unroll
    for (int o = 16; o; o >>= 1) sum += __shfl_xor_sync(0xffffffffu, sum, o);
    const float s = sum + g_cn[n];
    if (lane == 0) g_s[n * BATCH + row] = s;
#pragma unroll 4
    for (int it = 0; it < 16; it++) {
        const int k2 = it * 32 + lane;
        uint32_t h2 = shh[w][k2], l2 = shl[w][k2];
        __nv_bfloat162 hb = *(__nv_bfloat162*)&h2;
        __nv_bfloat162 lb = *(__nv_bfloat162*)&l2;
        float v0 = (__bfloat162float(hb.x) + __bfloat162float(lb.x)) * s;
        float v1 = (__bfloat162float(hb.y) + __bfloat162float(lb.y)) * s;
        __nv_bfloat16 hh0 = __float2bfloat16_rn(v0), hh1 = __float2bfloat16_rn(v1);
        __nv_bfloat16 ll0 = __float2bfloat16_rn(v0 - __bfloat162float(hh0));
        __nv_bfloat16 ll1 = __float2bfloat16_rn(v1 - __bfloat162float(hh1));
        *(__nv_bfloat162*)(g_vth + base + k2 * 2) = __halves2bfloat162(hh0, hh1);
        *(__nv_bfloat162*)(g_vtl + base + k2 * 2) = __halves2bfloat162(ll0, ll1);
    }
}

// ------------------------- launch ------------------------------------------
extern "C" void kernel_launch(void* const* d_in, const int* in_sizes, int n_in,
                              void* d_out, int out_size)
{
    const float* x    = (const float*)d_in[0];
    const int*   task = (const int*)  d_in[1];
    const float* Wb1  = (const float*)d_in[2];
    const float* bb1  = (const float*)d_in[3];
    const float* Wb2  = (const float*)d_in[4];
    const float* bb2  = (const float*)d_in[5];
    const float* We1  = (const float*)d_in[6];
    const float* be1  = (const float*)d_in[7];
    const float* We2  = (const float*)d_in[8];
    const float* be2  = (const float*)d_in[9];
    const float* Wv   = (const float*)d_in[10];
    const float* bv   = (const float*)d_in[11];
    const float* Wk   = (const float*)d_in[12];
    const float* bk   = (const float*)d_in[13];
    const float* Wq   = (const float*)d_in[14];
    const float* bq   = (const float*)d_in[15];
    const float* Wt1  = (const float*)d_in[16];
    const float* bt1  = (const float*)d_in[17];
    const float* Wl   = (const float*)d_in[18];
    const float* bl   = (const float*)d_in[19];
    float* out = (float*)d_out;

#define SYM(p, s) do { void* _t; cudaGetSymbolAddress(&_t, s); p = (decltype(p))_t; } while (0)
    __nv_bfloat16 *xh, *xl, *h1h, *h1l, *hh, *hl, *e1h, *e1l, *e2h, *e2l;
    __nv_bfloat16 *vth, *vtl, *rh, *rl, *th, *tl;
    __nv_bfloat16 *Wb1h, *Wb1l, *Wb2h, *Wb2l, *We1h, *We1l, *We2h, *We2l;
    __nv_bfloat16 *Wvh, *Wvl, *Wt1h, *Wt1l, *Wlh, *Wll;
    float *sc;
    SYM(xh, g_xh);  SYM(xl, g_xl);  SYM(h1h, g_h1h); SYM(h1l, g_h1l);
    SYM(hh, g_hh);  SYM(hl, g_hl);  SYM(e1h, g_e1h); SYM(e1l, g_e1l);
    SYM(e2h, g_e2h); SYM(e2l, g_e2l); SYM(vth, g_vth); SYM(vtl, g_vtl);
    SYM(rh, g_rh);  SYM(rl, g_rl);  SYM(th, g_th);  SYM(tl, g_tl);
    SYM(Wb1h, g_Wb1h); SYM(Wb1l, g_Wb1l); SYM(Wb2h, g_Wb2h); SYM(Wb2l, g_Wb2l);
    SYM(We1h, g_We1h); SYM(We1l, g_We1l); SYM(We2h, g_We2h); SYM(We2l, g_We2l);
    SYM(Wvh, g_Wvh); SYM(Wvl, g_Wvl); SYM(Wt1h, g_Wt1h); SYM(Wt1l, g_Wt1l);
    SYM(Wlh, g_Wlh); SYM(Wll, g_Wll); SYM(sc, g_s);

    cudaFuncSetAttribute(mma_gemm<EPI_RELU >, cudaFuncAttributeMaxDynamicSharedMemorySize, SMEMSZ);
    cudaFuncSetAttribute(mma_gemm<EPI_VSUM >, cudaFuncAttributeMaxDynamicSharedMemorySize, SMEMSZ);
    cudaFuncSetAttribute(mma_gemm<EPI_SPLIT>, cudaFuncAttributeMaxDynamicSharedMemorySize, SMEMSZ);

    dim3 tb(16, 16);

    split_k<<<(BATCH * OBSD + 255) / 256, 256>>>(x, xh, xl, BATCH * OBSD);
    transpose_split_k<<<dim3(OBSD / 32, DH / 32, 1),  tb>>>(Wb1, Wb1h, Wb1l, OBSD, DH, OBSD, 0);
    transpose_split_k<<<dim3(DH / 32, DH / 32, 1),    tb>>>(Wb2, Wb2h, Wb2l, DH, DH, DH, 0);
    transpose_split_k<<<dim3(DH / 32, DH / 32, NEXP), tb>>>(We1, We1h, We1l, DH, DH, DH, (size_t)DH * DH);

    mma_gemm<EPI_RELU><<<dim3(8, 32), 256, SMEMSZ>>>(
        xh, xl, OBSD, 0, Wb1h, Wb1l, OBSD, 0, bb1, 0, OBSD,
        nullptr, h1h, h1l, DH, 0, nullptr, nullptr);
    mma_gemm<EPI_RELU><<<dim3(8, 32), 256, SMEMSZ>>>(
        h1h, h1l, DH, 0, Wb2h, Wb2l, DH, 0, bb2, 0, DH,
        nullptr, hh, hl, DH, 0, nullptr, nullptr);

    // all experts e1: one GEMM, N = 8192
    mma_gemm<EPI_RELU><<<dim3(NDH8 / 128, 32), 256, SMEMSZ>>>(
        hh, hl, DH, 0, We1h, We1l, DH, 0, be1, 0, DH,
        nullptr, e1h, e1l, NDH8, 0, nullptr, nullptr);

    transpose_split_k<<<dim3(DH / 32, DH / 32, NEXP), tb>>>(We2, We2h, We2l, DH, DH, DH, (size_t)DH * DH);

    // all experts e2: z-batched block-diagonal GEMM
    mma_gemm<EPI_RELU><<<dim3(DH / 128, 32, NEXP), 256, SMEMSZ>>>(
        e1h, e1l, NDH8, DH, We2h, We2l, DH, DH * DH, be2, DH, DH,
        nullptr, e2h, e2l, NDH8, DH, nullptr, nullptr);

    prep_k<<<1, 256>>>(Wq, bq, bk, task);
    wn_k<<<NEXP * DH / 8, 256>>>(Wk);
    expkq_scale_k<<<dim3(BATCH / 8, NEXP), 256>>>();

    transpose_split_k<<<dim3(DH / 32, DVV / 32, NEXP), tb>>>(Wv, Wvh, Wvl, DH, DVV, NDH8, (size_t)DH);

    // fused v-sum: single GEMM over K = 8192, bias = sum_n bv[n]*s[n,b] in epilogue
    mma_gemm<EPI_VSUM><<<dim3(DVV / 128, 32), 256, SMEMSZ>>>(
        vth, vtl, NDH8, 0, Wvh, Wvl, NDH8, 0, nullptr, 0, NDH8,
        nullptr, rh, rl, DVV, 0, sc, bv);

    transpose_split_k<<<dim3(DVV / 32, DH / 32, 1), tb>>>(Wt1, Wt1h, Wt1l, DVV, DH, DVV, 0);
    mma_gemm<EPI_RELU><<<dim3(DH / 128, 32), 256, SMEMSZ>>>(
        rh, rl, DVV, 0, Wt1h, Wt1l, DVV, 0, bt1, 0, DVV,
        nullptr, th, tl, DH, 0, nullptr, nullptr);

    transpose_split_k<<<dim3(DH / 32, NOUT / 32, 1), tb>>>(Wl, Wlh, Wll, DH, NOUT, DH, 0);
    mma_gemm<EPI_SPLIT><<<dim3(1, 32), 256, SMEMSZ>>>(
        th, tl, DH, 0, Wlh, Wll, DH, 0, bl, 0, DH,
        out, nullptr, nullptr, NOUT, 0, nullptr, nullptr);
}